// round 5
// baseline (speedup 1.0000x reference)
#include <cuda_runtime.h>
#include <math.h>
#include <stdint.h>

// Problem constants
#define LEVEL   16
#define LENGTH  64
#define TOPK    2
#define SIZE    512
#define BATCH   32
#define NEG     (-1e8f)

#define LPOS    48              // LENGTH - LEVEL
#define NCELLS  904
#define NIDX    768             // LPOS * LEVEL
#define ROWS1   49152           // K*B*LPOS*LEVEL  (GEMM1 rows)
#define ROWS2   3072            // B*LPOS*K        (GEMM2 rows)
#define KSPLIT  4
#define NCELLS_BL 1536          // BATCH*LPOS
#define MAXCAND 16
#define MAXR    (NCELLS_BL * MAXCAND)
#define GUARD   1.5e-3f

// Output layout (float32, concatenated in reference return order)
#define OFF_H   0
#define OFF_S   1572864         // 3072*512
#define OFF_N   1575936
#define OFF_LK  1579008
#define OFF_RK  1582080

// Scratch (static device globals: allocation-free per harness rules)
__device__ float g_U[(size_t)ROWS1 * 512];              // ~100.7 MB
__device__ float g_AH[(size_t)ROWS1 * 512];             // gathered A hi (tf32)
__device__ float g_AL[(size_t)ROWS1 * 512];             // gathered A lo
__device__ float g_BH[512 * 512];
__device__ float g_BL[512 * 512];
__device__ float g_P[(size_t)KSPLIT * ROWS2 * 512];     // split-K partials
__device__ int   g_li[NIDX];
__device__ int   g_ri[NIDX];
__device__ int4  g_sel[ROWS2];
__device__ int   g_nrows;
__device__ int   g_rows[MAXR];          // (bl<<6)|z
__device__ float g_sexact[MAXR];
__device__ int   g_cellbase[NCELLS_BL];
__device__ int   g_cellcnt[NCELLS_BL];
__device__ int   g_cellflag[NCELLS_BL];

typedef unsigned long long u64t;

// packed f32x2 FMA: acc = a*b + acc (2 lanes per instruction)
#define FFMA2(acc, a, b) \
    asm("fma.rn.f32x2 %0, %1, %2, %0;" : "+l"(acc) : "l"(a), "l"(b))

__device__ __forceinline__ void mma_tf32(float d[4],
        uint32_t a0, uint32_t a1, uint32_t a2, uint32_t a3,
        uint32_t b0, uint32_t b1) {
    asm volatile(
        "mma.sync.aligned.m16n8k8.row.col.f32.tf32.tf32.f32 "
        "{%0,%1,%2,%3}, {%4,%5,%6,%7}, {%8,%9}, {%0,%1,%2,%3};"
        : "+f"(d[0]), "+f"(d[1]), "+f"(d[2]), "+f"(d[3])
        : "r"(a0), "r"(a1), "r"(a2), "r"(a3), "r"(b0), "r"(b1));
}

__device__ __forceinline__ float tf32_rna(float x) {
    uint32_t u;
    asm("cvt.rna.tf32.f32 %0, %1;" : "=r"(u) : "f"(x));
    return __uint_as_float(u);
}

// ---------------------------------------------------------------------------
// K0: index conversion + counter reset.
__global__ void conv_idx_kernel(const void* __restrict__ lraw,
                                const void* __restrict__ rraw) {
    if (blockIdx.x == 0 && threadIdx.x == 0) g_nrows = 0;
    const int* w = (const int*)lraw;
    bool is64 = (w[1] == 0 && w[2] == 64);
    int t = blockIdx.x * blockDim.x + threadIdx.x;
    if (t < NIDX) {
        if (is64) {
            g_li[t] = (int)((const long long*)lraw)[t];
            g_ri[t] = (int)((const long long*)rraw)[t];
        } else {
            g_li[t] = ((const int*)lraw)[t];
            g_ri[t] = ((const int*)rraw)[t];
        }
    }
}

// ---------------------------------------------------------------------------
// K1a: gather left-child rows and split into tf32 hi/lo planes (dense).
__global__ __launch_bounds__(256) void split_a_kernel(const float* __restrict__ chart_h) {
    size_t idx = (size_t)blockIdx.x * 256 + threadIdx.x;   // float4 units
    int r  = (int)(idx >> 7);
    int c4 = (int)(idx & 127) * 4;
    int k = r & 1;
    int t = r >> 1;
    int n = t & 15;
    int bl = t >> 4;
    int l = bl % LPOS, b = bl / LPOS;
    int cell = g_li[(l << 4) + n];
    float4 v = *(const float4*)(chart_h + (((size_t)(k * BATCH + b)) * NCELLS + cell) * SIZE + c4);
    float4 h, lo;
    h.x = tf32_rna(v.x); lo.x = tf32_rna(v.x - h.x);
    h.y = tf32_rna(v.y); lo.y = tf32_rna(v.y - h.y);
    h.z = tf32_rna(v.z); lo.z = tf32_rna(v.z - h.z);
    h.w = tf32_rna(v.w); lo.w = tf32_rna(v.w - h.w);
    *(float4*)(g_AH + (size_t)r * 512 + c4) = h;
    *(float4*)(g_AL + (size_t)r * 512 + c4) = lo;
}

// K1b: split mat into hi/lo planes.
__global__ __launch_bounds__(256) void split_mat_kernel(const float* __restrict__ mat) {
    size_t idx = (size_t)blockIdx.x * 256 + threadIdx.x;   // float4 units, 65536
    size_t off = idx * 4;
    float4 v = *(const float4*)(mat + off);
    float4 h, lo;
    h.x = tf32_rna(v.x); lo.x = tf32_rna(v.x - h.x);
    h.y = tf32_rna(v.y); lo.y = tf32_rna(v.y - h.y);
    h.z = tf32_rna(v.z); lo.z = tf32_rna(v.z - h.z);
    h.w = tf32_rna(v.w); lo.w = tf32_rna(v.w - h.w);
    *(float4*)(g_BH + off) = h;
    *(float4*)(g_BL + off) = lo;
}

// ---------------------------------------------------------------------------
// K2: U = A @ mat via 3xTF32 mma with {hi,lo}-paired smem and reg prefetch.
// Block 128x128, 8 warps (2x4), warp tile 64x32, BK=16.
__global__ __launch_bounds__(256, 1) void gemm1_mma_kernel(void) {
    __shared__ float As[128][20][2];    // [m][k(+pad)][hi,lo]; row stride 40 words == 8 mod 32
    __shared__ float Bs[16][132][2];    // [k][n(+pad)][hi,lo]; row stride 264 words == 8 mod 32

    int tid  = threadIdx.x;
    int row0 = blockIdx.y * 128;
    int col0 = blockIdx.x * 128;

    int ar = tid >> 1,  ac  = (tid & 1) * 8;   // A: 2 thr/row, 8 consecutive k
    int brr = tid >> 4, bcc = tid & 15;        // B: 16 thr/row, strided n (j*16)

    const float* pAH = g_AH + (size_t)(row0 + ar) * 512 + ac;
    const float* pAL = g_AL + (size_t)(row0 + ar) * 512 + ac;
    const float* pBH = g_BH + (size_t)brr * 512 + col0 + bcc;
    const float* pBL = g_BL + (size_t)brr * 512 + col0 + bcc;

    int wid = tid >> 5, lane = tid & 31;
    int wm = wid >> 2, wn = wid & 3;
    int gid = lane >> 2, tig = lane & 3;

    float d[4][4][4];
#pragma unroll
    for (int mf = 0; mf < 4; mf++)
#pragma unroll
        for (int nf = 0; nf < 4; nf++)
#pragma unroll
            for (int c = 0; c < 4; c++) d[mf][nf][c] = 0.f;

    float ah[8], al[8], bh[8], bl2[8];
    // prefetch kt = 0
    {
        float4 t0 = *(const float4*)(pAH);
        float4 t1 = *(const float4*)(pAH + 4);
        ah[0]=t0.x; ah[1]=t0.y; ah[2]=t0.z; ah[3]=t0.w;
        ah[4]=t1.x; ah[5]=t1.y; ah[6]=t1.z; ah[7]=t1.w;
        t0 = *(const float4*)(pAL);
        t1 = *(const float4*)(pAL + 4);
        al[0]=t0.x; al[1]=t0.y; al[2]=t0.z; al[3]=t0.w;
        al[4]=t1.x; al[5]=t1.y; al[6]=t1.z; al[7]=t1.w;
#pragma unroll
        for (int j = 0; j < 8; j++) bh[j]  = pBH[j * 16];
#pragma unroll
        for (int j = 0; j < 8; j++) bl2[j] = pBL[j * 16];
    }

    for (int kt = 0; kt < 32; kt++) {
        __syncthreads();
#pragma unroll
        for (int j = 0; j < 8; j++)
            *(float2*)&As[ar][ac + j][0] = make_float2(ah[j], al[j]);
#pragma unroll
        for (int j = 0; j < 8; j++)
            *(float2*)&Bs[brr][bcc + j * 16][0] = make_float2(bh[j], bl2[j]);
        __syncthreads();

        // prefetch next tile (clamped dummy on last iter)
        size_t kbn = (kt < 31) ? (size_t)(kt + 1) * 16 : 0;
        {
            float4 t0 = *(const float4*)(pAH + kbn);
            float4 t1 = *(const float4*)(pAH + kbn + 4);
            ah[0]=t0.x; ah[1]=t0.y; ah[2]=t0.z; ah[3]=t0.w;
            ah[4]=t1.x; ah[5]=t1.y; ah[6]=t1.z; ah[7]=t1.w;
            t0 = *(const float4*)(pAL + kbn);
            t1 = *(const float4*)(pAL + kbn + 4);
            al[0]=t0.x; al[1]=t0.y; al[2]=t0.z; al[3]=t0.w;
            al[4]=t1.x; al[5]=t1.y; al[6]=t1.z; al[7]=t1.w;
            const float* bHrow = pBH + kbn * 512;
            const float* bLrow = pBL + kbn * 512;
#pragma unroll
            for (int j = 0; j < 8; j++) bh[j]  = bHrow[j * 16];
#pragma unroll
            for (int j = 0; j < 8; j++) bl2[j] = bLrow[j * 16];
        }

#pragma unroll
        for (int kf = 0; kf < 2; kf++) {
            int k0 = kf * 8;
            uint32_t aH[4][4], aL[4][4], bH[4][2], bL[4][2];
#pragma unroll
            for (int mf = 0; mf < 4; mf++) {
                int m = wm * 64 + mf * 16 + gid;
                float2 f;
                f = *(float2*)&As[m][k0 + tig][0];
                aH[mf][0] = __float_as_uint(f.x); aL[mf][0] = __float_as_uint(f.y);
                f = *(float2*)&As[m + 8][k0 + tig][0];
                aH[mf][1] = __float_as_uint(f.x); aL[mf][1] = __float_as_uint(f.y);
                f = *(float2*)&As[m][k0 + tig + 4][0];
                aH[mf][2] = __float_as_uint(f.x); aL[mf][2] = __float_as_uint(f.y);
                f = *(float2*)&As[m + 8][k0 + tig + 4][0];
                aH[mf][3] = __float_as_uint(f.x); aL[mf][3] = __float_as_uint(f.y);
            }
#pragma unroll
            for (int nf = 0; nf < 4; nf++) {
                int nn = wn * 32 + nf * 8 + gid;
                float2 f;
                f = *(float2*)&Bs[k0 + tig][nn][0];
                bH[nf][0] = __float_as_uint(f.x); bL[nf][0] = __float_as_uint(f.y);
                f = *(float2*)&Bs[k0 + tig + 4][nn][0];
                bH[nf][1] = __float_as_uint(f.x); bL[nf][1] = __float_as_uint(f.y);
            }
#pragma unroll
            for (int mf = 0; mf < 4; mf++)
#pragma unroll
                for (int nf = 0; nf < 4; nf++) {
                    mma_tf32(d[mf][nf], aH[mf][0], aH[mf][1], aH[mf][2], aH[mf][3],
                             bL[nf][0], bL[nf][1]);
                    mma_tf32(d[mf][nf], aL[mf][0], aL[mf][1], aL[mf][2], aL[mf][3],
                             bH[nf][0], bH[nf][1]);
                    mma_tf32(d[mf][nf], aH[mf][0], aH[mf][1], aH[mf][2], aH[mf][3],
                             bH[nf][0], bH[nf][1]);
                }
        }
    }
#pragma unroll
    for (int mf = 0; mf < 4; mf++) {
        int rA = row0 + wm * 64 + mf * 16 + gid;
#pragma unroll
        for (int nf = 0; nf < 4; nf++) {
            int cA = col0 + wn * 32 + nf * 8 + tig * 2;
            *(float2*)(g_U + (size_t)rA * 512 + cA)       = make_float2(d[mf][nf][0], d[mf][nf][1]);
            *(float2*)(g_U + (size_t)(rA + 8) * 512 + cA) = make_float2(d[mf][nf][2], d[mf][nf][3]);
        }
    }
}

// ---------------------------------------------------------------------------
// K3: scores + top-2 with near-tie guard.
__global__ __launch_bounds__(256) void score_topk_kernel(
    const float* __restrict__ chart_h, const float* __restrict__ chart_s,
    float* __restrict__ out) {
    int bl = blockIdx.x;
    int b = bl / LPOS, l = bl % LPOS;
    int warp = threadIdx.x >> 5;
    int lane = threadIdx.x & 31;

    __shared__ float s[64];

    for (int n = warp; n < 16; n += 8) {
        int lcell = g_li[(l << 4) + n];
        int rcell = g_ri[(l << 4) + n];
        const float4* u0 = (const float4*)(g_U + ((((size_t)bl * 16) + n) * 2 + 0) * 512);
        const float4* u1 = u0 + 128;
        const float4* r0 = (const float4*)(chart_h + (((size_t)b) * NCELLS + rcell) * SIZE);
        const float4* r1 = (const float4*)(chart_h + (((size_t)(BATCH + b)) * NCELLS + rcell) * SIZE);
        float a00 = 0.f, a01 = 0.f, a10 = 0.f, a11 = 0.f;
#pragma unroll
        for (int it = 0; it < 4; it++) {
            int i = lane + it * 32;
            float4 x0 = u0[i], x1 = u1[i], y0 = r0[i], y1 = r1[i];
            a00 += x0.x*y0.x + x0.y*y0.y + x0.z*y0.z + x0.w*y0.w;
            a01 += x0.x*y1.x + x0.y*y1.y + x0.z*y1.z + x0.w*y1.w;
            a10 += x1.x*y0.x + x1.y*y0.y + x1.z*y0.z + x1.w*y0.w;
            a11 += x1.x*y1.x + x1.y*y1.y + x1.z*y1.z + x1.w*y1.w;
        }
#pragma unroll
        for (int o = 16; o; o >>= 1) {
            a00 += __shfl_xor_sync(0xffffffffu, a00, o);
            a01 += __shfl_xor_sync(0xffffffffu, a01, o);
            a10 += __shfl_xor_sync(0xffffffffu, a10, o);
            a11 += __shfl_xor_sync(0xffffffffu, a11, o);
        }
        if (lane == 0) {
            float ls0 = chart_s[(size_t)b * NCELLS + lcell];
            float ls1 = chart_s[(size_t)(BATCH + b) * NCELLS + lcell];
            float rs0 = chart_s[(size_t)b * NCELLS + rcell];
            float rs1 = chart_s[(size_t)(BATCH + b) * NCELLS + rcell];
            float v00 = a00 + ls0 + rs0, v01 = a01 + ls0 + rs1;
            float v10 = a10 + ls1 + rs0, v11 = a11 + ls1 + rs1;
            if (n == 0) { v10 = NEG; v11 = NEG; }   // penalty: catalan(1)=1
            s[n * 4 + 0] = v00; s[n * 4 + 1] = v01;
            s[n * 4 + 2] = v10; s[n * 4 + 3] = v11;
        }
    }
    __syncthreads();

    if (threadIdx.x == 0) {
        float b1 = -INFINITY; int i1 = 0;
        for (int z = 0; z < 64; z++) { float v = s[z]; if (v > b1) { b1 = v; i1 = z; } }
        float b2 = -INFINITY; int i2 = 0;
        for (int z = 0; z < 64; z++) {
            if (z == i1) continue;
            float v = s[z]; if (v > b2) { b2 = v; i2 = z; }
        }
        float b3 = -INFINITY;
        for (int z = 0; z < 64; z++) {
            if (z == i1 || z == i2) continue;
            float v = s[z]; if (v > b3) b3 = v;
        }
        if ((b1 - b2) < GUARD || (b2 - b3) < GUARD) {
            int cand[MAXCAND];
            int cnt = 0;
            cand[cnt++] = i1;
            cand[cnt++] = i2;
            float thr = b2 - GUARD;
            for (int z = 0; z < 64 && cnt < MAXCAND; z++) {
                if (z == i1 || z == i2) continue;
                if (s[z] >= thr) cand[cnt++] = z;
            }
            int base = atomicAdd(&g_nrows, cnt);
            g_cellbase[bl] = base;
            g_cellcnt[bl]  = cnt;
            g_cellflag[bl] = 1;
            for (int c = 0; c < cnt; c++) g_rows[base + c] = (bl << 6) | cand[c];
        } else {
            g_cellflag[bl] = 0;
            int o = bl * 2;
            out[OFF_S  + o]     = b1;
            out[OFF_S  + o + 1] = b2;
            out[OFF_N  + o]     = (float)(i1 >> 2);
            out[OFF_N  + o + 1] = (float)(i2 >> 2);
            out[OFF_LK + o]     = (float)((i1 >> 1) & 1);
            out[OFF_LK + o + 1] = (float)((i2 >> 1) & 1);
            out[OFF_RK + o]     = (float)(i1 & 1);
            out[OFF_RK + o + 1] = (float)(i2 & 1);
            g_sel[o]     = make_int4(i1 >> 2, (i1 >> 1) & 1, i1 & 1, 0);
            g_sel[o + 1] = make_int4(i2 >> 2, (i2 >> 1) & 1, i2 & 1, 0);
        }
    }
}

// ---------------------------------------------------------------------------
// K4: exact fp32 rescore for the rare near-tie candidates.
__global__ __launch_bounds__(256) void rescore_exact_kernel(
    const float* __restrict__ chart_h, const float* __restrict__ chart_s,
    const float* __restrict__ mat) {
    __shared__ float lh_s[512];
    __shared__ float red[8];
    int nrows = g_nrows;
    int t = threadIdx.x;

    for (int r = blockIdx.x; r < nrows; r += gridDim.x) {
        int code = g_rows[r];
        int bl = code >> 6, z = code & 63;
        int n = z >> 2, kl = (z >> 1) & 1, kr = z & 1;
        int b = bl / LPOS, l = bl % LPOS;
        int lcell = g_li[(l << 4) + n];
        int rcell = g_ri[(l << 4) + n];
        const float* lh = chart_h + (((size_t)(kl * BATCH + b)) * NCELLS + lcell) * SIZE;
        const float* rh = chart_h + (((size_t)(kr * BATCH + b)) * NCELLS + rcell) * SIZE;
        __syncthreads();
        lh_s[t] = lh[t];
        lh_s[t + 256] = lh[t + 256];
        __syncthreads();
        float u0 = 0.f, u1 = 0.f;
        for (int i = 0; i < 512; i++) {
            float a = lh_s[i];
            u0 += a * mat[(size_t)i * 512 + t];
            u1 += a * mat[(size_t)i * 512 + t + 256];
        }
        float part = u0 * rh[t] + u1 * rh[t + 256];
#pragma unroll
        for (int o = 16; o; o >>= 1) part += __shfl_xor_sync(0xffffffffu, part, o);
        if ((t & 31) == 0) red[t >> 5] = part;
        __syncthreads();
        if (t == 0) {
            float x = 0.f;
#pragma unroll
            for (int i = 0; i < 8; i++) x += red[i];
            float ls = chart_s[(size_t)(kl * BATCH + b) * NCELLS + lcell];
            float rs = chart_s[(size_t)(kr * BATCH + b) * NCELLS + rcell];
            g_sexact[r] = x + ls + rs;
        }
    }
}

// ---------------------------------------------------------------------------
// K5: for flagged cells, select exact top-2 and write outputs + g_sel.
__global__ __launch_bounds__(256) void fix_select_kernel(float* __restrict__ out) {
    int bl = blockIdx.x * 256 + threadIdx.x;
    if (bl >= NCELLS_BL) return;
    if (!g_cellflag[bl]) return;
    int base = g_cellbase[bl];
    int cnt  = g_cellcnt[bl];

    float s1 = -INFINITY, s2 = -INFINITY;
    int z1 = 64, z2 = 64;
    for (int c = 0; c < cnt; c++) {
        float v = g_sexact[base + c];
        int z = g_rows[base + c] & 63;
        if (v > s1 || (v == s1 && z < z1)) {
            s2 = s1; z2 = z1; s1 = v; z1 = z;
        } else if (v > s2 || (v == s2 && z < z2)) {
            s2 = v; z2 = z;
        }
    }
    int o = bl * 2;
    out[OFF_S  + o]     = s1;
    out[OFF_S  + o + 1] = s2;
    out[OFF_N  + o]     = (float)(z1 >> 2);
    out[OFF_N  + o + 1] = (float)(z2 >> 2);
    out[OFF_LK + o]     = (float)((z1 >> 1) & 1);
    out[OFF_LK + o + 1] = (float)((z2 >> 1) & 1);
    out[OFF_RK + o]     = (float)(z1 & 1);
    out[OFF_RK + o + 1] = (float)(z2 & 1);
    g_sel[o]     = make_int4(z1 >> 2, (z1 >> 1) & 1, z1 & 1, 0);
    g_sel[o + 1] = make_int4(z2 >> 2, (z2 >> 1) & 1, z2 & 1, 0);
}

// ---------------------------------------------------------------------------
// K6: split-K compose GEMM (FFMA2), partials -> g_P.
__global__ __launch_bounds__(256, 2) void gemm2_kernel(
    const float* __restrict__ chart_h, const float* __restrict__ Wc) {
    __shared__ float As2[16][256];
    __shared__ float Bs[16][128];
    __shared__ const float* Arow[128];

    int tid  = threadIdx.x;
    int row0 = blockIdx.y * 128;
    int col0 = blockIdx.x * 128;
    int ks   = blockIdx.z;
    int kbase = ks * 256;

    if (tid < 128) {
        int r = row0 + tid;
        int bl = r >> 1;
        int b = bl / LPOS, l = bl % LPOS;
        int4 sel = g_sel[r];
        const float* base;
        if (kbase < 512) {
            int lcell = g_li[(l << 4) + sel.x];
            base = chart_h + (((size_t)(sel.y * BATCH + b)) * NCELLS + lcell) * SIZE + kbase;
        } else {
            int rcell = g_ri[(l << 4) + sel.x];
            base = chart_h + (((size_t)(sel.z * BATCH + b)) * NCELLS + rcell) * SIZE + (kbase - 512);
        }
        Arow[tid] = base;
    }
    __syncthreads();

    u64t acc[8][4];
#pragma unroll
    for (int i = 0; i < 8; i++)
#pragma unroll
        for (int j = 0; j < 4; j++) acc[i][j] = 0ull;

    int arow  = tid >> 1;
    int ahalf = (tid & 1) * 8;
    int brow  = tid >> 5;
    int bcol4 = (tid & 31) * 4;
    int ty = tid >> 4, tx = tid & 15;

    for (int kk = 0; kk < 256; kk += 16) {
        float4 av0 = *(const float4*)(Arow[arow] + kk + ahalf);
        float4 av1 = *(const float4*)(Arow[arow] + kk + ahalf + 4);
        *(float2*)&As2[ahalf + 0][2 * arow] = make_float2(av0.x, av0.x);
        *(float2*)&As2[ahalf + 1][2 * arow] = make_float2(av0.y, av0.y);
        *(float2*)&As2[ahalf + 2][2 * arow] = make_float2(av0.z, av0.z);
        *(float2*)&As2[ahalf + 3][2 * arow] = make_float2(av0.w, av0.w);
        *(float2*)&As2[ahalf + 4][2 * arow] = make_float2(av1.x, av1.x);
        *(float2*)&As2[ahalf + 5][2 * arow] = make_float2(av1.y, av1.y);
        *(float2*)&As2[ahalf + 6][2 * arow] = make_float2(av1.z, av1.z);
        *(float2*)&As2[ahalf + 7][2 * arow] = make_float2(av1.w, av1.w);
        int kg = kbase + kk;
        *(float4*)(&Bs[brow][bcol4]) =
            *(const float4*)(Wc + (size_t)(kg + brow) * 512 + col0 + bcol4);
        *(float4*)(&Bs[brow + 8][bcol4]) =
            *(const float4*)(Wc + (size_t)(kg + brow + 8) * 512 + col0 + bcol4);
        __syncthreads();
#pragma unroll
        for (int kq = 0; kq < 16; kq++) {
            u64t a2[8], b2[4];
#pragma unroll
            for (int i = 0; i < 8; i++)
                a2[i] = *(const u64t*)&As2[kq][2 * (ty * 8 + i)];
#pragma unroll
            for (int j = 0; j < 4; j++)
                b2[j] = ((const u64t*)&Bs[kq][tx * 8])[j];
#pragma unroll
            for (int i = 0; i < 8; i++)
#pragma unroll
                for (int j = 0; j < 4; j++) FFMA2(acc[i][j], a2[i], b2[j]);
        }
        __syncthreads();
    }
#pragma unroll
    for (int i = 0; i < 8; i++) {
        int r = row0 + ty * 8 + i;
        u64t* crow = (u64t*)(g_P + ((size_t)ks * ROWS2 + r) * 512 + col0 + tx * 8);
#pragma unroll
        for (int j = 0; j < 4; j++) crow[j] = acc[i][j];
    }
}

// ---------------------------------------------------------------------------
// K7: combine split-K partials + bias + tanh + unit-norm, write topk_h.
__global__ __launch_bounds__(256) void combine_normalize_kernel(
    const float* __restrict__ bc, float* __restrict__ out) {
    int r = blockIdx.x;
    int t = threadIdx.x;
    const float* p = g_P + (size_t)r * 512;
    const size_t stride = (size_t)ROWS2 * 512;

    float v0 = bc[t]       + p[t]       + p[t + stride]       + p[t + 2*stride]       + p[t + 3*stride];
    float v1 = bc[t + 256] + p[t + 256] + p[t + 256 + stride] + p[t + 256 + 2*stride] + p[t + 256 + 3*stride];
    v0 = tanhf(v0);
    v1 = tanhf(v1);

    float ss = v0 * v0 + v1 * v1;
#pragma unroll
    for (int o = 16; o; o >>= 1) ss += __shfl_xor_sync(0xffffffffu, ss, o);
    __shared__ float red[8];
    __shared__ float s_inv;
    if ((t & 31) == 0) red[t >> 5] = ss;
    __syncthreads();
    if (t == 0) {
        float x = 0.f;
#pragma unroll
        for (int i = 0; i < 8; i++) x += red[i];
        s_inv = 1.0f / sqrtf(x);
    }
    __syncthreads();
    float inv = s_inv;
    out[OFF_H + (size_t)r * 512 + t]       = v0 * inv;
    out[OFF_H + (size_t)r * 512 + t + 256] = v1 * inv;
}

// ---------------------------------------------------------------------------
extern "C" void kernel_launch(void* const* d_in, const int* in_sizes, int n_in,
                              void* d_out, int out_size) {
    const float* chart_h = (const float*)d_in[0];
    const float* chart_s = (const float*)d_in[1];
    const void*  l_index = d_in[2];
    const void*  r_index = d_in[3];
    const float* mat     = (const float*)d_in[4];
    const float* Wc      = (const float*)d_in[5];
    const float* bc      = (const float*)d_in[6];
    float* out = (float*)d_out;

    conv_idx_kernel<<<3, 256>>>(l_index, r_index);
    split_a_kernel<<<ROWS1 * 512 / 4 / 256, 256>>>(chart_h);
    split_mat_kernel<<<512 * 512 / 4 / 256, 256>>>(mat);
    gemm1_mma_kernel<<<dim3(4, ROWS1 / 128), 256>>>();
    score_topk_kernel<<<NCELLS_BL, 256>>>(chart_h, chart_s, out);
    rescore_exact_kernel<<<128, 256>>>(chart_h, chart_s, mat);
    fix_select_kernel<<<6, 256>>>(out);
    gemm2_kernel<<<dim3(4, ROWS2 / 128, KSPLIT), 256>>>(chart_h, Wc);
    combine_normalize_kernel<<<ROWS2, 256>>>(bc, out);
}

// round 6
// speedup vs baseline: 1.2020x; 1.2020x over previous
#include <cuda_runtime.h>
#include <math.h>
#include <stdint.h>

// Problem constants
#define LEVEL   16
#define LENGTH  64
#define TOPK    2
#define SIZE    512
#define BATCH   32
#define NEG     (-1e8f)

#define LPOS    48              // LENGTH - LEVEL
#define NCELLS  904
#define NIDX    768             // LPOS * LEVEL
#define ROWS1   49152           // K*B*LPOS*LEVEL  (GEMM1 rows)
#define ROWS2   3072            // B*LPOS*K        (GEMM2 rows)
#define KSPLIT  4
#define NCELLS_BL 1536          // BATCH*LPOS
#define MAXCAND 16
#define MAXR    (NCELLS_BL * MAXCAND)
#define GUARD   1.5e-3f

// Output layout (float32, concatenated in reference return order)
#define OFF_H   0
#define OFF_S   1572864         // 3072*512
#define OFF_N   1575936
#define OFF_LK  1579008
#define OFF_RK  1582080

// gemm1 dynamic smem layout (floats)
#define A_PAD   20
#define B_PAD   136
#define A_BUF   (128 * A_PAD)           // 2560
#define B_BUF   (16 * B_PAD)            // 2176
#define SM_AH   0
#define SM_AL   (2 * A_BUF)
#define SM_BH   (4 * A_BUF)
#define SM_BL   (4 * A_BUF + 2 * B_BUF)
#define SMEM1_FLOATS (4 * A_BUF + 4 * B_BUF)     // 18944
#define SMEM1_BYTES  (SMEM1_FLOATS * 4)          // 75776

// Scratch (static device globals: allocation-free per harness rules)
__device__ float g_U[(size_t)ROWS1 * 512];              // ~100.7 MB
__device__ float g_AH[(size_t)ROWS1 * 512];             // gathered A hi (tf32)
__device__ float g_AL[(size_t)ROWS1 * 512];             // gathered A lo
__device__ float g_BH[512 * 512];
__device__ float g_BL[512 * 512];
__device__ float g_P[(size_t)KSPLIT * ROWS2 * 512];     // split-K partials
__device__ int   g_li[NIDX];
__device__ int   g_ri[NIDX];
__device__ int4  g_sel[ROWS2];
__device__ int   g_nrows;
__device__ int   g_rows[MAXR];          // (bl<<6)|z
__device__ float g_sexact[MAXR];
__device__ int   g_cellbase[NCELLS_BL];
__device__ int   g_cellcnt[NCELLS_BL];
__device__ int   g_cellflag[NCELLS_BL];

typedef unsigned long long u64t;

// packed f32x2 FMA: acc = a*b + acc (2 lanes per instruction)
#define FFMA2(acc, a, b) \
    asm("fma.rn.f32x2 %0, %1, %2, %0;" : "+l"(acc) : "l"(a), "l"(b))

#define CP_ASYNC16(dst32, src) \
    asm volatile("cp.async.cg.shared.global [%0], [%1], 16;" :: "r"(dst32), "l"(src))
#define CP_COMMIT()  asm volatile("cp.async.commit_group;")
#define CP_WAIT0()   asm volatile("cp.async.wait_group 0;")

__device__ __forceinline__ void mma_tf32(float d[4],
        uint32_t a0, uint32_t a1, uint32_t a2, uint32_t a3,
        uint32_t b0, uint32_t b1) {
    asm volatile(
        "mma.sync.aligned.m16n8k8.row.col.f32.tf32.tf32.f32 "
        "{%0,%1,%2,%3}, {%4,%5,%6,%7}, {%8,%9}, {%0,%1,%2,%3};"
        : "+f"(d[0]), "+f"(d[1]), "+f"(d[2]), "+f"(d[3])
        : "r"(a0), "r"(a1), "r"(a2), "r"(a3), "r"(b0), "r"(b1));
}

__device__ __forceinline__ float tf32_rna(float x) {
    uint32_t u;
    asm("cvt.rna.tf32.f32 %0, %1;" : "=r"(u) : "f"(x));
    return __uint_as_float(u);
}

// ---------------------------------------------------------------------------
// K0: index conversion + counter reset.
__global__ void conv_idx_kernel(const void* __restrict__ lraw,
                                const void* __restrict__ rraw) {
    if (blockIdx.x == 0 && threadIdx.x == 0) g_nrows = 0;
    const int* w = (const int*)lraw;
    bool is64 = (w[1] == 0 && w[2] == 64);
    int t = blockIdx.x * blockDim.x + threadIdx.x;
    if (t < NIDX) {
        if (is64) {
            g_li[t] = (int)((const long long*)lraw)[t];
            g_ri[t] = (int)((const long long*)rraw)[t];
        } else {
            g_li[t] = ((const int*)lraw)[t];
            g_ri[t] = ((const int*)rraw)[t];
        }
    }
}

// ---------------------------------------------------------------------------
// K1a: gather left-child rows and split into tf32 hi/lo planes (dense).
__global__ __launch_bounds__(256) void split_a_kernel(const float* __restrict__ chart_h) {
    size_t idx = (size_t)blockIdx.x * 256 + threadIdx.x;   // float4 units
    int r  = (int)(idx >> 7);
    int c4 = (int)(idx & 127) * 4;
    int k = r & 1;
    int t = r >> 1;
    int n = t & 15;
    int bl = t >> 4;
    int l = bl % LPOS, b = bl / LPOS;
    int cell = g_li[(l << 4) + n];
    float4 v = *(const float4*)(chart_h + (((size_t)(k * BATCH + b)) * NCELLS + cell) * SIZE + c4);
    float4 h, lo;
    h.x = tf32_rna(v.x); lo.x = tf32_rna(v.x - h.x);
    h.y = tf32_rna(v.y); lo.y = tf32_rna(v.y - h.y);
    h.z = tf32_rna(v.z); lo.z = tf32_rna(v.z - h.z);
    h.w = tf32_rna(v.w); lo.w = tf32_rna(v.w - h.w);
    *(float4*)(g_AH + (size_t)r * 512 + c4) = h;
    *(float4*)(g_AL + (size_t)r * 512 + c4) = lo;
}

// K1b: split mat into hi/lo planes.
__global__ __launch_bounds__(256) void split_mat_kernel(const float* __restrict__ mat) {
    size_t idx = (size_t)blockIdx.x * 256 + threadIdx.x;   // float4 units, 65536
    size_t off = idx * 4;
    float4 v = *(const float4*)(mat + off);
    float4 h, lo;
    h.x = tf32_rna(v.x); lo.x = tf32_rna(v.x - h.x);
    h.y = tf32_rna(v.y); lo.y = tf32_rna(v.y - h.y);
    h.z = tf32_rna(v.z); lo.z = tf32_rna(v.z - h.z);
    h.w = tf32_rna(v.w); lo.w = tf32_rna(v.w - h.w);
    *(float4*)(g_BH + off) = h;
    *(float4*)(g_BL + off) = lo;
}

// ---------------------------------------------------------------------------
// K2: U = A @ mat via 3xTF32 mma. cp.async double-buffered, 2 CTAs/SM.
// Block 128x128, 8 warps (2x4), warp tile 64x32, BK=16.
__global__ __launch_bounds__(256, 2) void gemm1_mma_kernel(void) {
    extern __shared__ float sm[];
    float* sAH = sm + SM_AH;
    float* sAL = sm + SM_AL;
    float* sBH = sm + SM_BH;
    float* sBL = sm + SM_BL;

    int tid  = threadIdx.x;
    int row0 = blockIdx.y * 128;
    int col0 = blockIdx.x * 128;

    // copy roles
    int ar = tid >> 1,  aw = (tid & 1) * 8;    // A: 2 thr/row, 8 consecutive k each
    int brr = tid >> 4, bw = (tid & 15) * 8;   // B: 16 thr/row, 8 consecutive n each

    const float* gAH = g_AH + (size_t)(row0 + ar) * 512 + aw;
    const float* gAL = g_AL + (size_t)(row0 + ar) * 512 + aw;
    const float* gBH = g_BH + (size_t)brr * 512 + col0 + bw;
    const float* gBL = g_BL + (size_t)brr * 512 + col0 + bw;

    uint32_t smb = (uint32_t)__cvta_generic_to_shared(sm);
    uint32_t dAH = smb + (SM_AH + ar * A_PAD + aw) * 4;
    uint32_t dAL = smb + (SM_AL + ar * A_PAD + aw) * 4;
    uint32_t dBH = smb + (SM_BH + brr * B_PAD + bw) * 4;
    uint32_t dBL = smb + (SM_BL + brr * B_PAD + bw) * 4;

    int wid = tid >> 5, lane = tid & 31;
    int wm = wid >> 2, wn = wid & 3;
    int gid = lane >> 2, tig = lane & 3;

    float d[4][4][4];
#pragma unroll
    for (int mf = 0; mf < 4; mf++)
#pragma unroll
        for (int nf = 0; nf < 4; nf++)
#pragma unroll
            for (int c = 0; c < 4; c++) d[mf][nf][c] = 0.f;

    // prefetch kt = 0 into buf 0
    {
        CP_ASYNC16(dAH,      gAH);
        CP_ASYNC16(dAH + 16, gAH + 4);
        CP_ASYNC16(dAL,      gAL);
        CP_ASYNC16(dAL + 16, gAL + 4);
        CP_ASYNC16(dBH,      gBH);
        CP_ASYNC16(dBH + 16, gBH + 4);
        CP_ASYNC16(dBL,      gBL);
        CP_ASYNC16(dBL + 16, gBL + 4);
        CP_COMMIT();
    }

    int buf = 0;
    for (int kt = 0; kt < 32; kt++) {
        CP_WAIT0();
        __syncthreads();

        if (kt < 31) {
            int nb = buf ^ 1;
            size_t goA = (size_t)(kt + 1) * 16;          // k offset in A plane
            size_t goB = (size_t)(kt + 1) * 16 * 512;    // row offset in B plane
            uint32_t oA = nb * A_BUF * 4;
            uint32_t oB = nb * B_BUF * 4;
            CP_ASYNC16(dAH + oA,      gAH + goA);
            CP_ASYNC16(dAH + oA + 16, gAH + goA + 4);
            CP_ASYNC16(dAL + oA,      gAL + goA);
            CP_ASYNC16(dAL + oA + 16, gAL + goA + 4);
            CP_ASYNC16(dBH + oB,      gBH + goB);
            CP_ASYNC16(dBH + oB + 16, gBH + goB + 4);
            CP_ASYNC16(dBL + oB,      gBL + goB);
            CP_ASYNC16(dBL + oB + 16, gBL + goB + 4);
            CP_COMMIT();
        }

        const float* AH = sAH + buf * A_BUF;
        const float* AL = sAL + buf * A_BUF;
        const float* BH = sBH + buf * B_BUF;
        const float* BL = sBL + buf * B_BUF;

#pragma unroll
        for (int kf = 0; kf < 2; kf++) {
            int k0 = kf * 8;
            uint32_t aH[4][4], aL[4][4];
#pragma unroll
            for (int mf = 0; mf < 4; mf++) {
                int m = wm * 64 + mf * 16 + gid;
                aH[mf][0] = __float_as_uint(AH[m * A_PAD + k0 + tig]);
                aH[mf][1] = __float_as_uint(AH[(m + 8) * A_PAD + k0 + tig]);
                aH[mf][2] = __float_as_uint(AH[m * A_PAD + k0 + tig + 4]);
                aH[mf][3] = __float_as_uint(AH[(m + 8) * A_PAD + k0 + tig + 4]);
                aL[mf][0] = __float_as_uint(AL[m * A_PAD + k0 + tig]);
                aL[mf][1] = __float_as_uint(AL[(m + 8) * A_PAD + k0 + tig]);
                aL[mf][2] = __float_as_uint(AL[m * A_PAD + k0 + tig + 4]);
                aL[mf][3] = __float_as_uint(AL[(m + 8) * A_PAD + k0 + tig + 4]);
            }
#pragma unroll
            for (int nf = 0; nf < 4; nf++) {
                int nn = wn * 32 + nf * 8 + gid;
                uint32_t bH0 = __float_as_uint(BH[(k0 + tig) * B_PAD + nn]);
                uint32_t bH1 = __float_as_uint(BH[(k0 + tig + 4) * B_PAD + nn]);
                uint32_t bL0 = __float_as_uint(BL[(k0 + tig) * B_PAD + nn]);
                uint32_t bL1 = __float_as_uint(BL[(k0 + tig + 4) * B_PAD + nn]);
#pragma unroll
                for (int mf = 0; mf < 4; mf++) {
                    mma_tf32(d[mf][nf], aH[mf][0], aH[mf][1], aH[mf][2], aH[mf][3],
                             bL0, bL1);
                    mma_tf32(d[mf][nf], aL[mf][0], aL[mf][1], aL[mf][2], aL[mf][3],
                             bH0, bH1);
                    mma_tf32(d[mf][nf], aH[mf][0], aH[mf][1], aH[mf][2], aH[mf][3],
                             bH0, bH1);
                }
            }
        }
        buf ^= 1;
    }

#pragma unroll
    for (int mf = 0; mf < 4; mf++) {
        int rA = row0 + wm * 64 + mf * 16 + gid;
#pragma unroll
        for (int nf = 0; nf < 4; nf++) {
            int cA = col0 + wn * 32 + nf * 8 + tig * 2;
            *(float2*)(g_U + (size_t)rA * 512 + cA)       = make_float2(d[mf][nf][0], d[mf][nf][1]);
            *(float2*)(g_U + (size_t)(rA + 8) * 512 + cA) = make_float2(d[mf][nf][2], d[mf][nf][3]);
        }
    }
}

// ---------------------------------------------------------------------------
// K3: scores + top-2 with near-tie guard.
__global__ __launch_bounds__(256) void score_topk_kernel(
    const float* __restrict__ chart_h, const float* __restrict__ chart_s,
    float* __restrict__ out) {
    int bl = blockIdx.x;
    int b = bl / LPOS, l = bl % LPOS;
    int warp = threadIdx.x >> 5;
    int lane = threadIdx.x & 31;

    __shared__ float s[64];

    for (int n = warp; n < 16; n += 8) {
        int lcell = g_li[(l << 4) + n];
        int rcell = g_ri[(l << 4) + n];
        const float4* u0 = (const float4*)(g_U + ((((size_t)bl * 16) + n) * 2 + 0) * 512);
        const float4* u1 = u0 + 128;
        const float4* r0 = (const float4*)(chart_h + (((size_t)b) * NCELLS + rcell) * SIZE);
        const float4* r1 = (const float4*)(chart_h + (((size_t)(BATCH + b)) * NCELLS + rcell) * SIZE);
        float a00 = 0.f, a01 = 0.f, a10 = 0.f, a11 = 0.f;
#pragma unroll
        for (int it = 0; it < 4; it++) {
            int i = lane + it * 32;
            float4 x0 = u0[i], x1 = u1[i], y0 = r0[i], y1 = r1[i];
            a00 += x0.x*y0.x + x0.y*y0.y + x0.z*y0.z + x0.w*y0.w;
            a01 += x0.x*y1.x + x0.y*y1.y + x0.z*y1.z + x0.w*y1.w;
            a10 += x1.x*y0.x + x1.y*y0.y + x1.z*y0.z + x1.w*y0.w;
            a11 += x1.x*y1.x + x1.y*y1.y + x1.z*y1.z + x1.w*y1.w;
        }
#pragma unroll
        for (int o = 16; o; o >>= 1) {
            a00 += __shfl_xor_sync(0xffffffffu, a00, o);
            a01 += __shfl_xor_sync(0xffffffffu, a01, o);
            a10 += __shfl_xor_sync(0xffffffffu, a10, o);
            a11 += __shfl_xor_sync(0xffffffffu, a11, o);
        }
        if (lane == 0) {
            float ls0 = chart_s[(size_t)b * NCELLS + lcell];
            float ls1 = chart_s[(size_t)(BATCH + b) * NCELLS + lcell];
            float rs0 = chart_s[(size_t)b * NCELLS + rcell];
            float rs1 = chart_s[(size_t)(BATCH + b) * NCELLS + rcell];
            float v00 = a00 + ls0 + rs0, v01 = a01 + ls0 + rs1;
            float v10 = a10 + ls1 + rs0, v11 = a11 + ls1 + rs1;
            if (n == 0) { v10 = NEG; v11 = NEG; }   // penalty: catalan(1)=1
            s[n * 4 + 0] = v00; s[n * 4 + 1] = v01;
            s[n * 4 + 2] = v10; s[n * 4 + 3] = v11;
        }
    }
    __syncthreads();

    if (threadIdx.x == 0) {
        float b1 = -INFINITY; int i1 = 0;
        for (int z = 0; z < 64; z++) { float v = s[z]; if (v > b1) { b1 = v; i1 = z; } }
        float b2 = -INFINITY; int i2 = 0;
        for (int z = 0; z < 64; z++) {
            if (z == i1) continue;
            float v = s[z]; if (v > b2) { b2 = v; i2 = z; }
        }
        float b3 = -INFINITY;
        for (int z = 0; z < 64; z++) {
            if (z == i1 || z == i2) continue;
            float v = s[z]; if (v > b3) b3 = v;
        }
        if ((b1 - b2) < GUARD || (b2 - b3) < GUARD) {
            int cand[MAXCAND];
            int cnt = 0;
            cand[cnt++] = i1;
            cand[cnt++] = i2;
            float thr = b2 - GUARD;
            for (int z = 0; z < 64 && cnt < MAXCAND; z++) {
                if (z == i1 || z == i2) continue;
                if (s[z] >= thr) cand[cnt++] = z;
            }
            int base = atomicAdd(&g_nrows, cnt);
            g_cellbase[bl] = base;
            g_cellcnt[bl]  = cnt;
            g_cellflag[bl] = 1;
            for (int c = 0; c < cnt; c++) g_rows[base + c] = (bl << 6) | cand[c];
        } else {
            g_cellflag[bl] = 0;
            int o = bl * 2;
            out[OFF_S  + o]     = b1;
            out[OFF_S  + o + 1] = b2;
            out[OFF_N  + o]     = (float)(i1 >> 2);
            out[OFF_N  + o + 1] = (float)(i2 >> 2);
            out[OFF_LK + o]     = (float)((i1 >> 1) & 1);
            out[OFF_LK + o + 1] = (float)((i2 >> 1) & 1);
            out[OFF_RK + o]     = (float)(i1 & 1);
            out[OFF_RK + o + 1] = (float)(i2 & 1);
            g_sel[o]     = make_int4(i1 >> 2, (i1 >> 1) & 1, i1 & 1, 0);
            g_sel[o + 1] = make_int4(i2 >> 2, (i2 >> 1) & 1, i2 & 1, 0);
        }
    }
}

// ---------------------------------------------------------------------------
// K4: exact fp32 rescore for the rare near-tie candidates.
__global__ __launch_bounds__(256) void rescore_exact_kernel(
    const float* __restrict__ chart_h, const float* __restrict__ chart_s,
    const float* __restrict__ mat) {
    __shared__ float lh_s[512];
    __shared__ float red[8];
    int nrows = g_nrows;
    int t = threadIdx.x;

    for (int r = blockIdx.x; r < nrows; r += gridDim.x) {
        int code = g_rows[r];
        int bl = code >> 6, z = code & 63;
        int n = z >> 2, kl = (z >> 1) & 1, kr = z & 1;
        int b = bl / LPOS, l = bl % LPOS;
        int lcell = g_li[(l << 4) + n];
        int rcell = g_ri[(l << 4) + n];
        const float* lh = chart_h + (((size_t)(kl * BATCH + b)) * NCELLS + lcell) * SIZE;
        const float* rh = chart_h + (((size_t)(kr * BATCH + b)) * NCELLS + rcell) * SIZE;
        __syncthreads();
        lh_s[t] = lh[t];
        lh_s[t + 256] = lh[t + 256];
        __syncthreads();
        float u0 = 0.f, u1 = 0.f;
        for (int i = 0; i < 512; i++) {
            float a = lh_s[i];
            u0 += a * mat[(size_t)i * 512 + t];
            u1 += a * mat[(size_t)i * 512 + t + 256];
        }
        float part = u0 * rh[t] + u1 * rh[t + 256];
#pragma unroll
        for (int o = 16; o; o >>= 1) part += __shfl_xor_sync(0xffffffffu, part, o);
        if ((t & 31) == 0) red[t >> 5] = part;
        __syncthreads();
        if (t == 0) {
            float x = 0.f;
#pragma unroll
            for (int i = 0; i < 8; i++) x += red[i];
            float ls = chart_s[(size_t)(kl * BATCH + b) * NCELLS + lcell];
            float rs = chart_s[(size_t)(kr * BATCH + b) * NCELLS + rcell];
            g_sexact[r] = x + ls + rs;
        }
    }
}

// ---------------------------------------------------------------------------
// K5: for flagged cells, select exact top-2 and write outputs + g_sel.
__global__ __launch_bounds__(256) void fix_select_kernel(float* __restrict__ out) {
    int bl = blockIdx.x * 256 + threadIdx.x;
    if (bl >= NCELLS_BL) return;
    if (!g_cellflag[bl]) return;
    int base = g_cellbase[bl];
    int cnt  = g_cellcnt[bl];

    float s1 = -INFINITY, s2 = -INFINITY;
    int z1 = 64, z2 = 64;
    for (int c = 0; c < cnt; c++) {
        float v = g_sexact[base + c];
        int z = g_rows[base + c] & 63;
        if (v > s1 || (v == s1 && z < z1)) {
            s2 = s1; z2 = z1; s1 = v; z1 = z;
        } else if (v > s2 || (v == s2 && z < z2)) {
            s2 = v; z2 = z;
        }
    }
    int o = bl * 2;
    out[OFF_S  + o]     = s1;
    out[OFF_S  + o + 1] = s2;
    out[OFF_N  + o]     = (float)(z1 >> 2);
    out[OFF_N  + o + 1] = (float)(z2 >> 2);
    out[OFF_LK + o]     = (float)((z1 >> 1) & 1);
    out[OFF_LK + o + 1] = (float)((z2 >> 1) & 1);
    out[OFF_RK + o]     = (float)(z1 & 1);
    out[OFF_RK + o + 1] = (float)(z2 & 1);
    g_sel[o]     = make_int4(z1 >> 2, (z1 >> 1) & 1, z1 & 1, 0);
    g_sel[o + 1] = make_int4(z2 >> 2, (z2 >> 1) & 1, z2 & 1, 0);
}

// ---------------------------------------------------------------------------
// K6: split-K compose GEMM (FFMA2), partials -> g_P.
__global__ __launch_bounds__(256, 2) void gemm2_kernel(
    const float* __restrict__ chart_h, const float* __restrict__ Wc) {
    __shared__ float As2[16][256];
    __shared__ float Bs[16][128];
    __shared__ const float* Arow[128];

    int tid  = threadIdx.x;
    int row0 = blockIdx.y * 128;
    int col0 = blockIdx.x * 128;
    int ks   = blockIdx.z;
    int kbase = ks * 256;

    if (tid < 128) {
        int r = row0 + tid;
        int bl = r >> 1;
        int b = bl / LPOS, l = bl % LPOS;
        int4 sel = g_sel[r];
        const float* base;
        if (kbase < 512) {
            int lcell = g_li[(l << 4) + sel.x];
            base = chart_h + (((size_t)(sel.y * BATCH + b)) * NCELLS + lcell) * SIZE + kbase;
        } else {
            int rcell = g_ri[(l << 4) + sel.x];
            base = chart_h + (((size_t)(sel.z * BATCH + b)) * NCELLS + rcell) * SIZE + (kbase - 512);
        }
        Arow[tid] = base;
    }
    __syncthreads();

    u64t acc[8][4];
#pragma unroll
    for (int i = 0; i < 8; i++)
#pragma unroll
        for (int j = 0; j < 4; j++) acc[i][j] = 0ull;

    int arow  = tid >> 1;
    int ahalf = (tid & 1) * 8;
    int brow  = tid >> 5;
    int bcol4 = (tid & 31) * 4;
    int ty = tid >> 4, tx = tid & 15;

    for (int kk = 0; kk < 256; kk += 16) {
        float4 av0 = *(const float4*)(Arow[arow] + kk + ahalf);
        float4 av1 = *(const float4*)(Arow[arow] + kk + ahalf + 4);
        *(float2*)&As2[ahalf + 0][2 * arow] = make_float2(av0.x, av0.x);
        *(float2*)&As2[ahalf + 1][2 * arow] = make_float2(av0.y, av0.y);
        *(float2*)&As2[ahalf + 2][2 * arow] = make_float2(av0.z, av0.z);
        *(float2*)&As2[ahalf + 3][2 * arow] = make_float2(av0.w, av0.w);
        *(float2*)&As2[ahalf + 4][2 * arow] = make_float2(av1.x, av1.x);
        *(float2*)&As2[ahalf + 5][2 * arow] = make_float2(av1.y, av1.y);
        *(float2*)&As2[ahalf + 6][2 * arow] = make_float2(av1.z, av1.z);
        *(float2*)&As2[ahalf + 7][2 * arow] = make_float2(av1.w, av1.w);
        int kg = kbase + kk;
        *(float4*)(&Bs[brow][bcol4]) =
            *(const float4*)(Wc + (size_t)(kg + brow) * 512 + col0 + bcol4);
        *(float4*)(&Bs[brow + 8][bcol4]) =
            *(const float4*)(Wc + (size_t)(kg + brow + 8) * 512 + col0 + bcol4);
        __syncthreads();
#pragma unroll
        for (int kq = 0; kq < 16; kq++) {
            u64t a2[8], b2[4];
#pragma unroll
            for (int i = 0; i < 8; i++)
                a2[i] = *(const u64t*)&As2[kq][2 * (ty * 8 + i)];
#pragma unroll
            for (int j = 0; j < 4; j++)
                b2[j] = ((const u64t*)&Bs[kq][tx * 8])[j];
#pragma unroll
            for (int i = 0; i < 8; i++)
#pragma unroll
                for (int j = 0; j < 4; j++) FFMA2(acc[i][j], a2[i], b2[j]);
        }
        __syncthreads();
    }
#pragma unroll
    for (int i = 0; i < 8; i++) {
        int r = row0 + ty * 8 + i;
        u64t* crow = (u64t*)(g_P + ((size_t)ks * ROWS2 + r) * 512 + col0 + tx * 8);
#pragma unroll
        for (int j = 0; j < 4; j++) crow[j] = acc[i][j];
    }
}

// ---------------------------------------------------------------------------
// K7: combine split-K partials + bias + tanh + unit-norm, write topk_h.
__global__ __launch_bounds__(256) void combine_normalize_kernel(
    const float* __restrict__ bc, float* __restrict__ out) {
    int r = blockIdx.x;
    int t = threadIdx.x;
    const float* p = g_P + (size_t)r * 512;
    const size_t stride = (size_t)ROWS2 * 512;

    float v0 = bc[t]       + p[t]       + p[t + stride]       + p[t + 2*stride]       + p[t + 3*stride];
    float v1 = bc[t + 256] + p[t + 256] + p[t + 256 + stride] + p[t + 256 + 2*stride] + p[t + 256 + 3*stride];
    v0 = tanhf(v0);
    v1 = tanhf(v1);

    float ss = v0 * v0 + v1 * v1;
#pragma unroll
    for (int o = 16; o; o >>= 1) ss += __shfl_xor_sync(0xffffffffu, ss, o);
    __shared__ float red[8];
    __shared__ float s_inv;
    if ((t & 31) == 0) red[t >> 5] = ss;
    __syncthreads();
    if (t == 0) {
        float x = 0.f;
#pragma unroll
        for (int i = 0; i < 8; i++) x += red[i];
        s_inv = 1.0f / sqrtf(x);
    }
    __syncthreads();
    float inv = s_inv;
    out[OFF_H + (size_t)r * 512 + t]       = v0 * inv;
    out[OFF_H + (size_t)r * 512 + t + 256] = v1 * inv;
}

// ---------------------------------------------------------------------------
extern "C" void kernel_launch(void* const* d_in, const int* in_sizes, int n_in,
                              void* d_out, int out_size) {
    const float* chart_h = (const float*)d_in[0];
    const float* chart_s = (const float*)d_in[1];
    const void*  l_index = d_in[2];
    const void*  r_index = d_in[3];
    const float* mat     = (const float*)d_in[4];
    const float* Wc      = (const float*)d_in[5];
    const float* bc      = (const float*)d_in[6];
    float* out = (float*)d_out;

    cudaFuncSetAttribute(gemm1_mma_kernel,
                         cudaFuncAttributeMaxDynamicSharedMemorySize, SMEM1_BYTES);

    conv_idx_kernel<<<3, 256>>>(l_index, r_index);
    split_a_kernel<<<ROWS1 * 512 / 4 / 256, 256>>>(chart_h);
    split_mat_kernel<<<512 * 512 / 4 / 256, 256>>>(mat);
    gemm1_mma_kernel<<<dim3(4, ROWS1 / 128), 256, SMEM1_BYTES>>>();
    score_topk_kernel<<<NCELLS_BL, 256>>>(chart_h, chart_s, out);
    rescore_exact_kernel<<<256, 256>>>(chart_h, chart_s, mat);
    fix_select_kernel<<<6, 256>>>(out);
    gemm2_kernel<<<dim3(4, ROWS2 / 128, KSPLIT), 256>>>(chart_h, Wc);
    combine_normalize_kernel<<<ROWS2, 256>>>(bc, out);
}

// round 7
// speedup vs baseline: 2.6651x; 2.2173x over previous
#include <cuda_runtime.h>
#include <math.h>
#include <stdint.h>

// Problem constants
#define LEVEL   16
#define LENGTH  64
#define TOPK    2
#define SIZE    512
#define BATCH   32
#define NEG     (-1e8f)

#define LPOS    48              // LENGTH - LEVEL
#define NCELLS  904
#define NIDX    768             // LPOS * LEVEL
#define ROWS1   49152           // K*B*LPOS*LEVEL  (GEMM1 rows)
#define ROWS2   3072            // B*LPOS*K        (GEMM2 rows)
#define KSPLIT  4
#define NCELLS_BL 1536          // BATCH*LPOS
#define MAXCAND 8
#define MAXR    (NCELLS_BL * MAXCAND)   // 12288
#define GUARD   0.25f

// Output layout (float32, concatenated in reference return order)
#define OFF_H   0
#define OFF_S   1572864         // 3072*512
#define OFF_N   1575936
#define OFF_LK  1579008
#define OFF_RK  1582080

// smem geometry for MMA kernels
#define A_PAD   20
#define B_PAD   136
#define A_BUF   (128 * A_PAD)
#define B_BUF   (16 * B_PAD)

// Scratch (static device globals: allocation-free per harness rules)
__device__ float g_U[(size_t)ROWS1 * 512];              // ~100.7 MB approx U
__device__ float g_Z[(size_t)MAXR * 512];               // ~25 MB exact rescore Z
__device__ float g_P[(size_t)KSPLIT * ROWS2 * 512];     // ~25 MB split-K partials
__device__ int   g_li[NIDX];
__device__ int   g_ri[NIDX];
__device__ int4  g_sel[ROWS2];
__device__ int   g_nrows;
__device__ int   g_rows[MAXR];          // (bl<<6)|z
__device__ float g_sexact[MAXR];
__device__ int   g_cellbase[NCELLS_BL];
__device__ int   g_cellcnt[NCELLS_BL];

#define CP_ASYNC16(dst32, src) \
    asm volatile("cp.async.cg.shared.global [%0], [%1], 16;" :: "r"(dst32), "l"(src))
#define CP_COMMIT()  asm volatile("cp.async.commit_group;")
#define CP_WAIT0()   asm volatile("cp.async.wait_group 0;")

__device__ __forceinline__ void mma_tf32(float d[4],
        uint32_t a0, uint32_t a1, uint32_t a2, uint32_t a3,
        uint32_t b0, uint32_t b1) {
    asm volatile(
        "mma.sync.aligned.m16n8k8.row.col.f32.tf32.tf32.f32 "
        "{%0,%1,%2,%3}, {%4,%5,%6,%7}, {%8,%9}, {%0,%1,%2,%3};"
        : "+f"(d[0]), "+f"(d[1]), "+f"(d[2]), "+f"(d[3])
        : "r"(a0), "r"(a1), "r"(a2), "r"(a3), "r"(b0), "r"(b1));
}

__device__ __forceinline__ float tf32_rna(float x) {
    uint32_t u;
    asm("cvt.rna.tf32.f32 %0, %1;" : "=r"(u) : "f"(x));
    return __uint_as_float(u);
}

// ---------------------------------------------------------------------------
// K0: index conversion + counter reset.
__global__ void conv_idx_kernel(const void* __restrict__ lraw,
                                const void* __restrict__ rraw) {
    if (blockIdx.x == 0 && threadIdx.x == 0) g_nrows = 0;
    const int* w = (const int*)lraw;
    bool is64 = (w[1] == 0 && w[2] == 64);
    int t = blockIdx.x * blockDim.x + threadIdx.x;
    if (t < NIDX) {
        if (is64) {
            g_li[t] = (int)((const long long*)lraw)[t];
            g_ri[t] = (int)((const long long*)rraw)[t];
        } else {
            g_li[t] = ((const int*)lraw)[t];
            g_ri[t] = ((const int*)rraw)[t];
        }
    }
}

// ---------------------------------------------------------------------------
// K1: U_approx = gather(chart_h left cells) @ mat, 1x tf32 (hw truncation).
// cp.async double buffer, in-kernel gather, 128x128 tile, BK=16.
__global__ __launch_bounds__(256, 2) void gemm1_mma_kernel(
    const float* __restrict__ chart_h, const float* __restrict__ mat) {
    __shared__ float sA[2][128][A_PAD];
    __shared__ float sB[2][16][B_PAD];
    __shared__ const float* Arow[128];

    int tid  = threadIdx.x;
    int row0 = blockIdx.y * 128;
    int col0 = blockIdx.x * 128;

    if (tid < 128) {
        int r = row0 + tid;
        int k = r & 1;
        int t = r >> 1;
        int n = t & 15;
        int bl = t >> 4;
        int l = bl % LPOS, b = bl / LPOS;
        int cell = g_li[(l << 4) + n];
        Arow[tid] = chart_h + (((size_t)(k * BATCH + b)) * NCELLS + cell) * SIZE;
    }
    __syncthreads();

    int ar = tid >> 1,  aw = (tid & 1) * 8;
    int brr = tid >> 4, bw = (tid & 15) * 8;
    const float* gA = Arow[ar] + aw;
    const float* gB = mat + (size_t)brr * 512 + col0 + bw;

    uint32_t dA = (uint32_t)__cvta_generic_to_shared(&sA[0][ar][aw]);
    uint32_t dB = (uint32_t)__cvta_generic_to_shared(&sB[0][brr][bw]);

    int wid = tid >> 5, lane = tid & 31;
    int wm = wid >> 2, wn = wid & 3;
    int gid = lane >> 2, tig = lane & 3;

    float d[4][4][4];
#pragma unroll
    for (int mf = 0; mf < 4; mf++)
#pragma unroll
        for (int nf = 0; nf < 4; nf++)
#pragma unroll
            for (int c = 0; c < 4; c++) d[mf][nf][c] = 0.f;

    CP_ASYNC16(dA, gA);
    CP_ASYNC16(dA + 16, gA + 4);
    CP_ASYNC16(dB, gB);
    CP_ASYNC16(dB + 16, gB + 4);
    CP_COMMIT();

    int buf = 0;
    for (int kt = 0; kt < 32; kt++) {
        CP_WAIT0();
        __syncthreads();
        if (kt < 31) {
            int nb = buf ^ 1;
            size_t goA = (size_t)(kt + 1) * 16;
            size_t goB = (size_t)(kt + 1) * 16 * 512;
            uint32_t oA = (uint32_t)(nb ? A_BUF * 4 : -(A_BUF * 4));
            uint32_t oB = (uint32_t)(nb ? B_BUF * 4 : -(B_BUF * 4));
            uint32_t nA = dA + (nb ? A_BUF * 4 : 0) - (buf ? A_BUF * 4 : 0);
            uint32_t nB = dB + (nb ? B_BUF * 4 : 0) - (buf ? B_BUF * 4 : 0);
            (void)oA; (void)oB;
            CP_ASYNC16(nA, gA + goA);
            CP_ASYNC16(nA + 16, gA + goA + 4);
            CP_ASYNC16(nB, gB + goB);
            CP_ASYNC16(nB + 16, gB + goB + 4);
            CP_COMMIT();
            dA = nA; dB = nB;
        }

        const float (*A)[A_PAD] = sA[buf];
        const float (*B)[B_PAD] = sB[buf];
#pragma unroll
        for (int kf = 0; kf < 2; kf++) {
            int k0 = kf * 8;
            uint32_t a[4][4];
#pragma unroll
            for (int mf = 0; mf < 4; mf++) {
                int m = wm * 64 + mf * 16 + gid;
                a[mf][0] = __float_as_uint(A[m][k0 + tig]);
                a[mf][1] = __float_as_uint(A[m + 8][k0 + tig]);
                a[mf][2] = __float_as_uint(A[m][k0 + tig + 4]);
                a[mf][3] = __float_as_uint(A[m + 8][k0 + tig + 4]);
            }
#pragma unroll
            for (int nf = 0; nf < 4; nf++) {
                int nn = wn * 32 + nf * 8 + gid;
                uint32_t b0 = __float_as_uint(B[k0 + tig][nn]);
                uint32_t b1 = __float_as_uint(B[k0 + tig + 4][nn]);
#pragma unroll
                for (int mf = 0; mf < 4; mf++)
                    mma_tf32(d[mf][nf], a[mf][0], a[mf][1], a[mf][2], a[mf][3], b0, b1);
            }
        }
        buf ^= 1;
    }

#pragma unroll
    for (int mf = 0; mf < 4; mf++) {
        int rA = row0 + wm * 64 + mf * 16 + gid;
#pragma unroll
        for (int nf = 0; nf < 4; nf++) {
            int cA = col0 + wn * 32 + nf * 8 + tig * 2;
            *(float2*)(g_U + (size_t)rA * 512 + cA)       = make_float2(d[mf][nf][0], d[mf][nf][1]);
            *(float2*)(g_U + (size_t)(rA + 8) * 512 + cA) = make_float2(d[mf][nf][2], d[mf][nf][3]);
        }
    }
}

// ---------------------------------------------------------------------------
// K2: approx scores + nomination. Every cell nominates top-2 plus all combos
// within GUARD of approx-2nd; exact values come from the rescore pipeline.
__global__ __launch_bounds__(256) void score_topk_kernel(
    const float* __restrict__ chart_h, const float* __restrict__ chart_s) {
    int bl = blockIdx.x;
    int b = bl / LPOS, l = bl % LPOS;
    int warp = threadIdx.x >> 5;
    int lane = threadIdx.x & 31;

    __shared__ float s[64];

    for (int n = warp; n < 16; n += 8) {
        int lcell = g_li[(l << 4) + n];
        int rcell = g_ri[(l << 4) + n];
        const float4* u0 = (const float4*)(g_U + ((((size_t)bl * 16) + n) * 2 + 0) * 512);
        const float4* u1 = u0 + 128;
        const float4* r0 = (const float4*)(chart_h + (((size_t)b) * NCELLS + rcell) * SIZE);
        const float4* r1 = (const float4*)(chart_h + (((size_t)(BATCH + b)) * NCELLS + rcell) * SIZE);
        float a00 = 0.f, a01 = 0.f, a10 = 0.f, a11 = 0.f;
#pragma unroll
        for (int it = 0; it < 4; it++) {
            int i = lane + it * 32;
            float4 x0 = u0[i], x1 = u1[i], y0 = r0[i], y1 = r1[i];
            a00 += x0.x*y0.x + x0.y*y0.y + x0.z*y0.z + x0.w*y0.w;
            a01 += x0.x*y1.x + x0.y*y1.y + x0.z*y1.z + x0.w*y1.w;
            a10 += x1.x*y0.x + x1.y*y0.y + x1.z*y0.z + x1.w*y0.w;
            a11 += x1.x*y1.x + x1.y*y1.y + x1.z*y1.z + x1.w*y1.w;
        }
#pragma unroll
        for (int o = 16; o; o >>= 1) {
            a00 += __shfl_xor_sync(0xffffffffu, a00, o);
            a01 += __shfl_xor_sync(0xffffffffu, a01, o);
            a10 += __shfl_xor_sync(0xffffffffu, a10, o);
            a11 += __shfl_xor_sync(0xffffffffu, a11, o);
        }
        if (lane == 0) {
            float ls0 = chart_s[(size_t)b * NCELLS + lcell];
            float ls1 = chart_s[(size_t)(BATCH + b) * NCELLS + lcell];
            float rs0 = chart_s[(size_t)b * NCELLS + rcell];
            float rs1 = chart_s[(size_t)(BATCH + b) * NCELLS + rcell];
            float v00 = a00 + ls0 + rs0, v01 = a01 + ls0 + rs1;
            float v10 = a10 + ls1 + rs0, v11 = a11 + ls1 + rs1;
            if (n == 0) { v10 = NEG; v11 = NEG; }   // penalty: catalan(1)=1
            s[n * 4 + 0] = v00; s[n * 4 + 1] = v01;
            s[n * 4 + 2] = v10; s[n * 4 + 3] = v11;
        }
    }
    __syncthreads();

    if (threadIdx.x == 0) {
        float b1 = -INFINITY; int i1 = 0;
        for (int z = 0; z < 64; z++) { float v = s[z]; if (v > b1) { b1 = v; i1 = z; } }
        float b2 = -INFINITY; int i2 = 0;
        for (int z = 0; z < 64; z++) {
            if (z == i1) continue;
            float v = s[z]; if (v > b2) { b2 = v; i2 = z; }
        }
        int cand[MAXCAND];
        int cnt = 0;
        cand[cnt++] = i1;
        cand[cnt++] = i2;
        float thr = b2 - GUARD;
        for (int z = 0; z < 64 && cnt < MAXCAND; z++) {
            if (z == i1 || z == i2) continue;
            if (s[z] >= thr) cand[cnt++] = z;
        }
        int base = atomicAdd(&g_nrows, cnt);
        g_cellbase[bl] = base;
        g_cellcnt[bl]  = cnt;
        for (int c = 0; c < cnt; c++) g_rows[base + c] = (bl << 6) | cand[c];
    }
}

// ---------------------------------------------------------------------------
// K3: 3xTF32 rescore GEMM: Z = lh_cand @ mat (fp32-grade). Same skeleton as
// gemm1 but with in-fragment hi/lo split and 3 MMAs per fragment pair.
__global__ __launch_bounds__(256, 2) void rescore_gemm_kernel(
    const float* __restrict__ chart_h, const float* __restrict__ mat) {
    int nrows = g_nrows;
    if ((int)(blockIdx.y * 128) >= nrows) return;

    __shared__ float sA[2][128][A_PAD];
    __shared__ float sB[2][16][B_PAD];
    __shared__ const float* Arow[128];

    int tid  = threadIdx.x;
    int row0 = blockIdx.y * 128;
    int col0 = blockIdx.x * 128;

    if (tid < 128) {
        int r = row0 + tid;
        const float* p = chart_h;
        if (r < nrows) {
            int code = g_rows[r];
            int bl = code >> 6, z = code & 63;
            int n = z >> 2, kl = (z >> 1) & 1;
            int b = bl / LPOS, l = bl % LPOS;
            int lcell = g_li[(l << 4) + n];
            p = chart_h + (((size_t)(kl * BATCH + b)) * NCELLS + lcell) * SIZE;
        }
        Arow[tid] = p;
    }
    __syncthreads();

    int ar = tid >> 1,  aw = (tid & 1) * 8;
    int brr = tid >> 4, bw = (tid & 15) * 8;
    const float* gA = Arow[ar] + aw;
    const float* gB = mat + (size_t)brr * 512 + col0 + bw;

    uint32_t dA = (uint32_t)__cvta_generic_to_shared(&sA[0][ar][aw]);
    uint32_t dB = (uint32_t)__cvta_generic_to_shared(&sB[0][brr][bw]);

    int wid = tid >> 5, lane = tid & 31;
    int wm = wid >> 2, wn = wid & 3;
    int gid = lane >> 2, tig = lane & 3;

    float d[4][4][4];
#pragma unroll
    for (int mf = 0; mf < 4; mf++)
#pragma unroll
        for (int nf = 0; nf < 4; nf++)
#pragma unroll
            for (int c = 0; c < 4; c++) d[mf][nf][c] = 0.f;

    CP_ASYNC16(dA, gA);
    CP_ASYNC16(dA + 16, gA + 4);
    CP_ASYNC16(dB, gB);
    CP_ASYNC16(dB + 16, gB + 4);
    CP_COMMIT();

    int buf = 0;
    for (int kt = 0; kt < 32; kt++) {
        CP_WAIT0();
        __syncthreads();
        if (kt < 31) {
            int nb = buf ^ 1;
            size_t goA = (size_t)(kt + 1) * 16;
            size_t goB = (size_t)(kt + 1) * 16 * 512;
            uint32_t nA = dA + (nb ? A_BUF * 4 : 0) - (buf ? A_BUF * 4 : 0);
            uint32_t nB = dB + (nb ? B_BUF * 4 : 0) - (buf ? B_BUF * 4 : 0);
            CP_ASYNC16(nA, gA + goA);
            CP_ASYNC16(nA + 16, gA + goA + 4);
            CP_ASYNC16(nB, gB + goB);
            CP_ASYNC16(nB + 16, gB + goB + 4);
            CP_COMMIT();
            dA = nA; dB = nB;
        }

        const float (*A)[A_PAD] = sA[buf];
        const float (*B)[B_PAD] = sB[buf];
#pragma unroll
        for (int kf = 0; kf < 2; kf++) {
            int k0 = kf * 8;
            uint32_t aH[4][4], aL[4][4];
#pragma unroll
            for (int mf = 0; mf < 4; mf++) {
                int m = wm * 64 + mf * 16 + gid;
                float v0 = A[m][k0 + tig];
                float v1 = A[m + 8][k0 + tig];
                float v2 = A[m][k0 + tig + 4];
                float v3 = A[m + 8][k0 + tig + 4];
                float h0 = tf32_rna(v0), h1 = tf32_rna(v1);
                float h2 = tf32_rna(v2), h3 = tf32_rna(v3);
                aH[mf][0] = __float_as_uint(h0); aL[mf][0] = __float_as_uint(tf32_rna(v0 - h0));
                aH[mf][1] = __float_as_uint(h1); aL[mf][1] = __float_as_uint(tf32_rna(v1 - h1));
                aH[mf][2] = __float_as_uint(h2); aL[mf][2] = __float_as_uint(tf32_rna(v2 - h2));
                aH[mf][3] = __float_as_uint(h3); aL[mf][3] = __float_as_uint(tf32_rna(v3 - h3));
            }
#pragma unroll
            for (int nf = 0; nf < 4; nf++) {
                int nn = wn * 32 + nf * 8 + gid;
                float w0 = B[k0 + tig][nn];
                float w1 = B[k0 + tig + 4][nn];
                float bh0f = tf32_rna(w0), bh1f = tf32_rna(w1);
                uint32_t bh0 = __float_as_uint(bh0f);
                uint32_t bh1 = __float_as_uint(bh1f);
                uint32_t bl0 = __float_as_uint(tf32_rna(w0 - bh0f));
                uint32_t bl1 = __float_as_uint(tf32_rna(w1 - bh1f));
#pragma unroll
                for (int mf = 0; mf < 4; mf++) {
                    mma_tf32(d[mf][nf], aH[mf][0], aH[mf][1], aH[mf][2], aH[mf][3], bl0, bl1);
                    mma_tf32(d[mf][nf], aL[mf][0], aL[mf][1], aL[mf][2], aL[mf][3], bh0, bh1);
                    mma_tf32(d[mf][nf], aH[mf][0], aH[mf][1], aH[mf][2], aH[mf][3], bh0, bh1);
                }
            }
        }
        buf ^= 1;
    }

#pragma unroll
    for (int mf = 0; mf < 4; mf++) {
        int rA = row0 + wm * 64 + mf * 16 + gid;
#pragma unroll
        for (int nf = 0; nf < 4; nf++) {
            int cA = col0 + wn * 32 + nf * 8 + tig * 2;
            *(float2*)(g_Z + (size_t)rA * 512 + cA)       = make_float2(d[mf][nf][0], d[mf][nf][1]);
            *(float2*)(g_Z + (size_t)(rA + 8) * 512 + cA) = make_float2(d[mf][nf][2], d[mf][nf][3]);
        }
    }
}

// ---------------------------------------------------------------------------
// K4: exact score = Z[row] . rh + ls + rs. One warp per candidate row.
__global__ __launch_bounds__(256) void rescore_dot_kernel(
    const float* __restrict__ chart_h, const float* __restrict__ chart_s) {
    int nrows = g_nrows;
    int row = blockIdx.x * 8 + (threadIdx.x >> 5);
    if (row >= nrows) return;
    int lane = threadIdx.x & 31;

    int code = g_rows[row];
    int bl = code >> 6, z = code & 63;
    int n = z >> 2, kl = (z >> 1) & 1, kr = z & 1;
    int b = bl / LPOS, l = bl % LPOS;
    int lcell = g_li[(l << 4) + n];
    int rcell = g_ri[(l << 4) + n];

    const float4* zp = (const float4*)(g_Z + (size_t)row * 512);
    const float4* rh = (const float4*)(chart_h + (((size_t)(kr * BATCH + b)) * NCELLS + rcell) * SIZE);
    float a = 0.f;
#pragma unroll
    for (int it = 0; it < 4; it++) {
        int i = lane + it * 32;
        float4 x = zp[i], y = rh[i];
        a += x.x*y.x + x.y*y.y + x.z*y.z + x.w*y.w;
    }
#pragma unroll
    for (int o = 16; o; o >>= 1) a += __shfl_xor_sync(0xffffffffu, a, o);
    if (lane == 0) {
        float ls = chart_s[(size_t)(kl * BATCH + b) * NCELLS + lcell];
        float rs = chart_s[(size_t)(kr * BATCH + b) * NCELLS + rcell];
        g_sexact[row] = a + ls + rs;
    }
}

// ---------------------------------------------------------------------------
// K5: per cell select exact top-2; write outputs + g_sel (all cells).
__global__ __launch_bounds__(256) void fix_select_kernel(float* __restrict__ out) {
    int bl = blockIdx.x * 256 + threadIdx.x;
    if (bl >= NCELLS_BL) return;
    int base = g_cellbase[bl];
    int cnt  = g_cellcnt[bl];

    float s1 = -INFINITY, s2 = -INFINITY;
    int z1 = 64, z2 = 64;
    for (int c = 0; c < cnt; c++) {
        float v = g_sexact[base + c];
        int z = g_rows[base + c] & 63;
        if (v > s1 || (v == s1 && z < z1)) {
            s2 = s1; z2 = z1; s1 = v; z1 = z;
        } else if (v > s2 || (v == s2 && z < z2)) {
            s2 = v; z2 = z;
        }
    }
    int o = bl * 2;
    out[OFF_S  + o]     = s1;
    out[OFF_S  + o + 1] = s2;
    out[OFF_N  + o]     = (float)(z1 >> 2);
    out[OFF_N  + o + 1] = (float)(z2 >> 2);
    out[OFF_LK + o]     = (float)((z1 >> 1) & 1);
    out[OFF_LK + o + 1] = (float)((z2 >> 1) & 1);
    out[OFF_RK + o]     = (float)(z1 & 1);
    out[OFF_RK + o + 1] = (float)(z2 & 1);
    g_sel[o]     = make_int4(z1 >> 2, (z1 >> 1) & 1, z1 & 1, 0);
    g_sel[o + 1] = make_int4(z2 >> 2, (z2 >> 1) & 1, z2 & 1, 0);
}

// ---------------------------------------------------------------------------
// K6: compose GEMM, 1x tf32 MMA, split-K=4 -> partials g_P.
__global__ __launch_bounds__(256, 2) void gemm2_mma_kernel(
    const float* __restrict__ chart_h, const float* __restrict__ Wc) {
    __shared__ float sA[2][128][A_PAD];
    __shared__ float sB[2][16][B_PAD];
    __shared__ const float* Arow[128];

    int tid  = threadIdx.x;
    int row0 = blockIdx.y * 128;
    int col0 = blockIdx.x * 128;
    int ks   = blockIdx.z;
    int kbase = ks * 256;

    if (tid < 128) {
        int r = row0 + tid;
        int bl = r >> 1;
        int b = bl / LPOS, l = bl % LPOS;
        int4 sel = g_sel[r];
        const float* base;
        if (kbase < 512) {
            int lcell = g_li[(l << 4) + sel.x];
            base = chart_h + (((size_t)(sel.y * BATCH + b)) * NCELLS + lcell) * SIZE + kbase;
        } else {
            int rcell = g_ri[(l << 4) + sel.x];
            base = chart_h + (((size_t)(sel.z * BATCH + b)) * NCELLS + rcell) * SIZE + (kbase - 512);
        }
        Arow[tid] = base;
    }
    __syncthreads();

    int ar = tid >> 1,  aw = (tid & 1) * 8;
    int brr = tid >> 4, bw = (tid & 15) * 8;
    const float* gA = Arow[ar] + aw;
    const float* gB = Wc + (size_t)(kbase + brr) * 512 + col0 + bw;

    uint32_t dA = (uint32_t)__cvta_generic_to_shared(&sA[0][ar][aw]);
    uint32_t dB = (uint32_t)__cvta_generic_to_shared(&sB[0][brr][bw]);

    int wid = tid >> 5, lane = tid & 31;
    int wm = wid >> 2, wn = wid & 3;
    int gid = lane >> 2, tig = lane & 3;

    float d[4][4][4];
#pragma unroll
    for (int mf = 0; mf < 4; mf++)
#pragma unroll
        for (int nf = 0; nf < 4; nf++)
#pragma unroll
            for (int c = 0; c < 4; c++) d[mf][nf][c] = 0.f;

    CP_ASYNC16(dA, gA);
    CP_ASYNC16(dA + 16, gA + 4);
    CP_ASYNC16(dB, gB);
    CP_ASYNC16(dB + 16, gB + 4);
    CP_COMMIT();

    int buf = 0;
    for (int kt = 0; kt < 16; kt++) {
        CP_WAIT0();
        __syncthreads();
        if (kt < 15) {
            int nb = buf ^ 1;
            size_t goA = (size_t)(kt + 1) * 16;
            size_t goB = (size_t)(kt + 1) * 16 * 512;
            uint32_t nA = dA + (nb ? A_BUF * 4 : 0) - (buf ? A_BUF * 4 : 0);
            uint32_t nB = dB + (nb ? B_BUF * 4 : 0) - (buf ? B_BUF * 4 : 0);
            CP_ASYNC16(nA, gA + goA);
            CP_ASYNC16(nA + 16, gA + goA + 4);
            CP_ASYNC16(nB, gB + goB);
            CP_ASYNC16(nB + 16, gB + goB + 4);
            CP_COMMIT();
            dA = nA; dB = nB;
        }

        const float (*A)[A_PAD] = sA[buf];
        const float (*B)[B_PAD] = sB[buf];
#pragma unroll
        for (int kf = 0; kf < 2; kf++) {
            int k0 = kf * 8;
            uint32_t a[4][4];
#pragma unroll
            for (int mf = 0; mf < 4; mf++) {
                int m = wm * 64 + mf * 16 + gid;
                a[mf][0] = __float_as_uint(A[m][k0 + tig]);
                a[mf][1] = __float_as_uint(A[m + 8][k0 + tig]);
                a[mf][2] = __float_as_uint(A[m][k0 + tig + 4]);
                a[mf][3] = __float_as_uint(A[m + 8][k0 + tig + 4]);
            }
#pragma unroll
            for (int nf = 0; nf < 4; nf++) {
                int nn = wn * 32 + nf * 8 + gid;
                uint32_t b0 = __float_as_uint(B[k0 + tig][nn]);
                uint32_t b1 = __float_as_uint(B[k0 + tig + 4][nn]);
#pragma unroll
                for (int mf = 0; mf < 4; mf++)
                    mma_tf32(d[mf][nf], a[mf][0], a[mf][1], a[mf][2], a[mf][3], b0, b1);
            }
        }
        buf ^= 1;
    }

#pragma unroll
    for (int mf = 0; mf < 4; mf++) {
        int rA = row0 + wm * 64 + mf * 16 + gid;
#pragma unroll
        for (int nf = 0; nf < 4; nf++) {
            int cA = col0 + wn * 32 + nf * 8 + tig * 2;
            float* p = g_P + ((size_t)ks * ROWS2 + rA) * 512 + cA;
            *(float2*)p                = make_float2(d[mf][nf][0], d[mf][nf][1]);
            *(float2*)(p + 8 * 512)    = make_float2(d[mf][nf][2], d[mf][nf][3]);
        }
    }
}

// ---------------------------------------------------------------------------
// K7: combine split-K partials + bias + tanh + unit-norm, write topk_h.
__global__ __launch_bounds__(256) void combine_normalize_kernel(
    const float* __restrict__ bc, float* __restrict__ out) {
    int r = blockIdx.x;
    int t = threadIdx.x;
    const float* p = g_P + (size_t)r * 512;
    const size_t stride = (size_t)ROWS2 * 512;

    float v0 = bc[t]       + p[t]       + p[t + stride]       + p[t + 2*stride]       + p[t + 3*stride];
    float v1 = bc[t + 256] + p[t + 256] + p[t + 256 + stride] + p[t + 256 + 2*stride] + p[t + 256 + 3*stride];
    v0 = tanhf(v0);
    v1 = tanhf(v1);

    float ss = v0 * v0 + v1 * v1;
#pragma unroll
    for (int o = 16; o; o >>= 1) ss += __shfl_xor_sync(0xffffffffu, ss, o);
    __shared__ float red[8];
    __shared__ float s_inv;
    if ((t & 31) == 0) red[t >> 5] = ss;
    __syncthreads();
    if (t == 0) {
        float x = 0.f;
#pragma unroll
        for (int i = 0; i < 8; i++) x += red[i];
        s_inv = 1.0f / sqrtf(x);
    }
    __syncthreads();
    float inv = s_inv;
    out[OFF_H + (size_t)r * 512 + t]       = v0 * inv;
    out[OFF_H + (size_t)r * 512 + t + 256] = v1 * inv;
}

// ---------------------------------------------------------------------------
extern "C" void kernel_launch(void* const* d_in, const int* in_sizes, int n_in,
                              void* d_out, int out_size) {
    const float* chart_h = (const float*)d_in[0];
    const float* chart_s = (const float*)d_in[1];
    const void*  l_index = d_in[2];
    const void*  r_index = d_in[3];
    const float* mat     = (const float*)d_in[4];
    const float* Wc      = (const float*)d_in[5];
    const float* bc      = (const float*)d_in[6];
    float* out = (float*)d_out;

    conv_idx_kernel<<<3, 256>>>(l_index, r_index);
    gemm1_mma_kernel<<<dim3(4, ROWS1 / 128), 256>>>(chart_h, mat);
    score_topk_kernel<<<NCELLS_BL, 256>>>(chart_h, chart_s);
    rescore_gemm_kernel<<<dim3(4, MAXR / 128), 256>>>(chart_h, mat);
    rescore_dot_kernel<<<MAXR / 8, 256>>>(chart_h, chart_s);
    fix_select_kernel<<<6, 256>>>(out);
    gemm2_mma_kernel<<<dim3(4, ROWS2 / 128, KSPLIT), 256>>>(chart_h, Wc);
    combine_normalize_kernel<<<ROWS2, 256>>>(bc, out);
}

// round 8
// speedup vs baseline: 2.8483x; 1.0687x over previous
#include <cuda_runtime.h>
#include <math.h>
#include <stdint.h>

// Problem constants
#define LEVEL   16
#define LENGTH  64
#define TOPK    2
#define SIZE    512
#define BATCH   32
#define NEG     (-1e8f)

#define LPOS    48              // LENGTH - LEVEL
#define NCELLS  904
#define NIDX    768             // LPOS * LEVEL
#define ROWS1   49152           // K*B*LPOS*LEVEL  (GEMM1 rows)
#define ROWS2   3072            // B*LPOS*K        (GEMM2 rows)
#define KSPLIT  4
#define NCELLS_BL 1536          // BATCH*LPOS
#define MAXCAND 12
#define MAXR    (NCELLS_BL * MAXCAND)   // 18432
#define GUARD   0.12f

// Output layout (float32, concatenated in reference return order)
#define OFF_H   0
#define OFF_S   1572864         // 3072*512
#define OFF_N   1575936
#define OFF_LK  1579008
#define OFF_RK  1582080

// smem geometry: rescore kernel (round-7 layout)
#define A_PAD   20
#define B_PAD   136
#define A_BUF   (128 * A_PAD)
#define B_BUF   (16 * B_PAD)
// smem geometry: LDSM kernels (A and B both [128][20])
#define TPAD    20
#define TBUF_BYTES (128 * TPAD * 4)     // 10240

// Scratch (static device globals: allocation-free per harness rules)
__device__ float g_U[(size_t)ROWS1 * 512];              // ~100.7 MB approx U
__device__ float g_Z[(size_t)MAXR * 512];               // ~37.7 MB rescore Z
__device__ float g_P[(size_t)KSPLIT * ROWS2 * 512];     // ~25 MB split-K partials
__device__ float g_matT[512 * 512];                     // mat^T [n][k]
__device__ float g_WcT[512 * 1024];                     // Wc^T  [n][k]
__device__ int   g_li[NIDX];
__device__ int   g_ri[NIDX];
__device__ int4  g_sel[ROWS2];
__device__ int   g_nrows;
__device__ int   g_rows[MAXR];          // (bl<<6)|z
__device__ float g_sexact[MAXR];
__device__ int   g_cellbase[NCELLS_BL];
__device__ int   g_cellcnt[NCELLS_BL];

#define CP_ASYNC16(dst32, src) \
    asm volatile("cp.async.cg.shared.global [%0], [%1], 16;" :: "r"(dst32), "l"(src))
#define CP_COMMIT()  asm volatile("cp.async.commit_group;")
#define CP_WAIT0()   asm volatile("cp.async.wait_group 0;")

#define LDSM4(r0, r1, r2, r3, a) \
    asm volatile("ldmatrix.sync.aligned.m8n8.x4.shared.b16 {%0,%1,%2,%3}, [%4];" \
        : "=r"(r0), "=r"(r1), "=r"(r2), "=r"(r3) : "r"(a))

__device__ __forceinline__ void mma_tf32(float d[4],
        uint32_t a0, uint32_t a1, uint32_t a2, uint32_t a3,
        uint32_t b0, uint32_t b1) {
    asm volatile(
        "mma.sync.aligned.m16n8k8.row.col.f32.tf32.tf32.f32 "
        "{%0,%1,%2,%3}, {%4,%5,%6,%7}, {%8,%9}, {%0,%1,%2,%3};"
        : "+f"(d[0]), "+f"(d[1]), "+f"(d[2]), "+f"(d[3])
        : "r"(a0), "r"(a1), "r"(a2), "r"(a3), "r"(b0), "r"(b1));
}

__device__ __forceinline__ float tf32_rna(float x) {
    uint32_t u;
    asm("cvt.rna.tf32.f32 %0, %1;" : "=r"(u) : "f"(x));
    return __uint_as_float(u);
}

// ---------------------------------------------------------------------------
// K0: index conversion + counter reset.
__global__ void conv_idx_kernel(const void* __restrict__ lraw,
                                const void* __restrict__ rraw) {
    if (blockIdx.x == 0 && threadIdx.x == 0) g_nrows = 0;
    const int* w = (const int*)lraw;
    bool is64 = (w[1] == 0 && w[2] == 64);
    int t = blockIdx.x * blockDim.x + threadIdx.x;
    if (t < NIDX) {
        if (is64) {
            g_li[t] = (int)((const long long*)lraw)[t];
            g_ri[t] = (int)((const long long*)rraw)[t];
        } else {
            g_li[t] = ((const int*)lraw)[t];
            g_ri[t] = ((const int*)rraw)[t];
        }
    }
}

// ---------------------------------------------------------------------------
// K0b: tiled transpose, dst[c][r] = src[r][c].  block (32,8).
__global__ void transpose_kernel(const float* __restrict__ src,
                                 float* __restrict__ dst, int rows, int cols) {
    __shared__ float tile[32][33];
    int bx = blockIdx.x * 32;   // col base
    int by = blockIdx.y * 32;   // row base
    int tx = threadIdx.x, ty = threadIdx.y;
#pragma unroll
    for (int i = 0; i < 32; i += 8)
        tile[ty + i][tx] = src[(size_t)(by + ty + i) * cols + bx + tx];
    __syncthreads();
#pragma unroll
    for (int i = 0; i < 32; i += 8)
        dst[(size_t)(bx + ty + i) * rows + by + tx] = tile[tx][ty + i];
}

// ---------------------------------------------------------------------------
// K1: U_approx = gather(chart_h left cells) @ mat, 1x tf32, LDSM fragments.
// A smem [m 128][k 16] pad 20; B smem [n 128][k 16] pad 20 (from matT).
__global__ __launch_bounds__(256, 2) void gemm1_mma_kernel(
    const float* __restrict__ chart_h) {
    __shared__ float sA[2][128][TPAD];
    __shared__ float sB[2][128][TPAD];
    __shared__ const float* Arow[128];

    int tid  = threadIdx.x;
    int row0 = blockIdx.y * 128;
    int col0 = blockIdx.x * 128;

    if (tid < 128) {
        int r = row0 + tid;
        int k = r & 1;
        int t = r >> 1;
        int n = t & 15;
        int bl = t >> 4;
        int l = bl % LPOS, b = bl / LPOS;
        int cell = g_li[(l << 4) + n];
        Arow[tid] = chart_h + (((size_t)(k * BATCH + b)) * NCELLS + cell) * SIZE;
    }
    __syncthreads();

    int cr = tid >> 1, cw = (tid & 1) * 8;     // copy role: row, 8-float half
    const float* gA = Arow[cr] + cw;
    const float* gB = g_matT + (size_t)(col0 + cr) * 512 + cw;

    uint32_t aBase = (uint32_t)__cvta_generic_to_shared(&sA[0][0][0]);
    uint32_t bBase = (uint32_t)__cvta_generic_to_shared(&sB[0][0][0]);
    uint32_t dA = aBase + (cr * TPAD + cw) * 4;
    uint32_t dB = bBase + (cr * TPAD + cw) * 4;

    int wid = tid >> 5, lane = tid & 31;
    int wm = wid >> 2, wn = wid & 3;
    int gid = lane >> 2, tig = lane & 3;
    int t4 = lane >> 3, lr = lane & 7;

    uint32_t aAddr[4], bAddr[2];
    {
        int arow_off = (t4 & 1) * 8 + lr, acol = (t4 >> 1) * 4;
        int brow_off = ((t4 >> 1) * 8) + lr, bcol = (t4 & 1) * 4;
#pragma unroll
        for (int mf = 0; mf < 4; mf++)
            aAddr[mf] = aBase + ((wm * 64 + mf * 16 + arow_off) * TPAD + acol) * 4;
#pragma unroll
        for (int p = 0; p < 2; p++)
            bAddr[p] = bBase + ((wn * 32 + p * 16 + brow_off) * TPAD + bcol) * 4;
    }

    float d[4][4][4];
#pragma unroll
    for (int mf = 0; mf < 4; mf++)
#pragma unroll
        for (int nf = 0; nf < 4; nf++)
#pragma unroll
            for (int c = 0; c < 4; c++) d[mf][nf][c] = 0.f;

    CP_ASYNC16(dA, gA);
    CP_ASYNC16(dA + 16, gA + 4);
    CP_ASYNC16(dB, gB);
    CP_ASYNC16(dB + 16, gB + 4);
    CP_COMMIT();

    int buf = 0;
    for (int kt = 0; kt < 32; kt++) {
        CP_WAIT0();
        __syncthreads();
        if (kt < 31) {
            int nb = buf ^ 1;
            size_t go = (size_t)(kt + 1) * 16;
            uint32_t nA = dA + nb * TBUF_BYTES;
            uint32_t nB = dB + nb * TBUF_BYTES;
            CP_ASYNC16(nA, gA + go);
            CP_ASYNC16(nA + 16, gA + go + 4);
            CP_ASYNC16(nB, gB + go);
            CP_ASYNC16(nB + 16, gB + go + 4);
            CP_COMMIT();
        }

        uint32_t boff = buf * TBUF_BYTES;
#pragma unroll
        for (int kf = 0; kf < 2; kf++) {
            uint32_t koff = boff + kf * 32;
            uint32_t a[4][4], bb[4][2];
#pragma unroll
            for (int mf = 0; mf < 4; mf++)
                LDSM4(a[mf][0], a[mf][1], a[mf][2], a[mf][3], aAddr[mf] + koff);
#pragma unroll
            for (int p = 0; p < 2; p++)
                LDSM4(bb[2 * p][0], bb[2 * p][1], bb[2 * p + 1][0], bb[2 * p + 1][1],
                      bAddr[p] + koff);
#pragma unroll
            for (int nf = 0; nf < 4; nf++)
#pragma unroll
                for (int mf = 0; mf < 4; mf++)
                    mma_tf32(d[mf][nf], a[mf][0], a[mf][1], a[mf][2], a[mf][3],
                             bb[nf][0], bb[nf][1]);
        }
        buf ^= 1;
    }

#pragma unroll
    for (int mf = 0; mf < 4; mf++) {
        int rA = row0 + wm * 64 + mf * 16 + gid;
#pragma unroll
        for (int nf = 0; nf < 4; nf++) {
            int cA = col0 + wn * 32 + nf * 8 + tig * 2;
            *(float2*)(g_U + (size_t)rA * 512 + cA)       = make_float2(d[mf][nf][0], d[mf][nf][1]);
            *(float2*)(g_U + (size_t)(rA + 8) * 512 + cA) = make_float2(d[mf][nf][2], d[mf][nf][3]);
        }
    }
}

// ---------------------------------------------------------------------------
// K2: approx scores + nomination: top-2 plus all combos within GUARD of
// approx-2nd; exact values come from the rescore pipeline.
__global__ __launch_bounds__(256) void score_topk_kernel(
    const float* __restrict__ chart_h, const float* __restrict__ chart_s) {
    int bl = blockIdx.x;
    int b = bl / LPOS, l = bl % LPOS;
    int warp = threadIdx.x >> 5;
    int lane = threadIdx.x & 31;

    __shared__ float s[64];

    for (int n = warp; n < 16; n += 8) {
        int lcell = g_li[(l << 4) + n];
        int rcell = g_ri[(l << 4) + n];
        const float4* u0 = (const float4*)(g_U + ((((size_t)bl * 16) + n) * 2 + 0) * 512);
        const float4* u1 = u0 + 128;
        const float4* r0 = (const float4*)(chart_h + (((size_t)b) * NCELLS + rcell) * SIZE);
        const float4* r1 = (const float4*)(chart_h + (((size_t)(BATCH + b)) * NCELLS + rcell) * SIZE);
        float a00 = 0.f, a01 = 0.f, a10 = 0.f, a11 = 0.f;
#pragma unroll
        for (int it = 0; it < 4; it++) {
            int i = lane + it * 32;
            float4 x0 = u0[i], x1 = u1[i], y0 = r0[i], y1 = r1[i];
            a00 += x0.x*y0.x + x0.y*y0.y + x0.z*y0.z + x0.w*y0.w;
            a01 += x0.x*y1.x + x0.y*y1.y + x0.z*y1.z + x0.w*y1.w;
            a10 += x1.x*y0.x + x1.y*y0.y + x1.z*y0.z + x1.w*y0.w;
            a11 += x1.x*y1.x + x1.y*y1.y + x1.z*y1.z + x1.w*y1.w;
        }
#pragma unroll
        for (int o = 16; o; o >>= 1) {
            a00 += __shfl_xor_sync(0xffffffffu, a00, o);
            a01 += __shfl_xor_sync(0xffffffffu, a01, o);
            a10 += __shfl_xor_sync(0xffffffffu, a10, o);
            a11 += __shfl_xor_sync(0xffffffffu, a11, o);
        }
        if (lane == 0) {
            float ls0 = chart_s[(size_t)b * NCELLS + lcell];
            float ls1 = chart_s[(size_t)(BATCH + b) * NCELLS + lcell];
            float rs0 = chart_s[(size_t)b * NCELLS + rcell];
            float rs1 = chart_s[(size_t)(BATCH + b) * NCELLS + rcell];
            float v00 = a00 + ls0 + rs0, v01 = a01 + ls0 + rs1;
            float v10 = a10 + ls1 + rs0, v11 = a11 + ls1 + rs1;
            if (n == 0) { v10 = NEG; v11 = NEG; }   // penalty: catalan(1)=1
            s[n * 4 + 0] = v00; s[n * 4 + 1] = v01;
            s[n * 4 + 2] = v10; s[n * 4 + 3] = v11;
        }
    }
    __syncthreads();

    if (threadIdx.x == 0) {
        float b1 = -INFINITY; int i1 = 0;
        for (int z = 0; z < 64; z++) { float v = s[z]; if (v > b1) { b1 = v; i1 = z; } }
        float b2 = -INFINITY; int i2 = 0;
        for (int z = 0; z < 64; z++) {
            if (z == i1) continue;
            float v = s[z]; if (v > b2) { b2 = v; i2 = z; }
        }
        int cand[MAXCAND];
        int cnt = 0;
        cand[cnt++] = i1;
        cand[cnt++] = i2;
        float thr = b2 - GUARD;
        for (int z = 0; z < 64 && cnt < MAXCAND; z++) {
            if (z == i1 || z == i2) continue;
            if (s[z] >= thr) cand[cnt++] = z;
        }
        int base = atomicAdd(&g_nrows, cnt);
        g_cellbase[bl] = base;
        g_cellcnt[bl]  = cnt;
        for (int c = 0; c < cnt; c++) g_rows[base + c] = (bl << 6) | cand[c];
    }
}

// ---------------------------------------------------------------------------
// K3: 3xTF32 rescore GEMM: Z = lh_cand @ mat (fp32-grade), in-fragment split.
__global__ __launch_bounds__(256, 2) void rescore_gemm_kernel(
    const float* __restrict__ chart_h, const float* __restrict__ mat) {
    int nrows = g_nrows;
    if ((int)(blockIdx.y * 128) >= nrows) return;

    __shared__ float sA[2][128][A_PAD];
    __shared__ float sB[2][16][B_PAD];
    __shared__ const float* Arow[128];

    int tid  = threadIdx.x;
    int row0 = blockIdx.y * 128;
    int col0 = blockIdx.x * 128;

    if (tid < 128) {
        int r = row0 + tid;
        const float* p = chart_h;
        if (r < nrows) {
            int code = g_rows[r];
            int bl = code >> 6, z = code & 63;
            int n = z >> 2, kl = (z >> 1) & 1;
            int b = bl / LPOS, l = bl % LPOS;
            int lcell = g_li[(l << 4) + n];
            p = chart_h + (((size_t)(kl * BATCH + b)) * NCELLS + lcell) * SIZE;
        }
        Arow[tid] = p;
    }
    __syncthreads();

    int ar = tid >> 1,  aw = (tid & 1) * 8;
    int brr = tid >> 4, bw = (tid & 15) * 8;
    const float* gA = Arow[ar] + aw;
    const float* gB = mat + (size_t)brr * 512 + col0 + bw;

    uint32_t dA = (uint32_t)__cvta_generic_to_shared(&sA[0][ar][aw]);
    uint32_t dB = (uint32_t)__cvta_generic_to_shared(&sB[0][brr][bw]);

    int wid = tid >> 5, lane = tid & 31;
    int wm = wid >> 2, wn = wid & 3;
    int gid = lane >> 2, tig = lane & 3;

    float d[4][4][4];
#pragma unroll
    for (int mf = 0; mf < 4; mf++)
#pragma unroll
        for (int nf = 0; nf < 4; nf++)
#pragma unroll
            for (int c = 0; c < 4; c++) d[mf][nf][c] = 0.f;

    CP_ASYNC16(dA, gA);
    CP_ASYNC16(dA + 16, gA + 4);
    CP_ASYNC16(dB, gB);
    CP_ASYNC16(dB + 16, gB + 4);
    CP_COMMIT();

    int buf = 0;
    for (int kt = 0; kt < 32; kt++) {
        CP_WAIT0();
        __syncthreads();
        if (kt < 31) {
            int nb = buf ^ 1;
            size_t goA = (size_t)(kt + 1) * 16;
            size_t goB = (size_t)(kt + 1) * 16 * 512;
            uint32_t nA = dA + (nb ? A_BUF * 4 : 0) - (buf ? A_BUF * 4 : 0);
            uint32_t nB = dB + (nb ? B_BUF * 4 : 0) - (buf ? B_BUF * 4 : 0);
            CP_ASYNC16(nA, gA + goA);
            CP_ASYNC16(nA + 16, gA + goA + 4);
            CP_ASYNC16(nB, gB + goB);
            CP_ASYNC16(nB + 16, gB + goB + 4);
            CP_COMMIT();
            dA = nA; dB = nB;
        }

        const float (*A)[A_PAD] = sA[buf];
        const float (*B)[B_PAD] = sB[buf];
#pragma unroll
        for (int kf = 0; kf < 2; kf++) {
            int k0 = kf * 8;
            uint32_t aH[4][4], aL[4][4];
#pragma unroll
            for (int mf = 0; mf < 4; mf++) {
                int m = wm * 64 + mf * 16 + gid;
                float v0 = A[m][k0 + tig];
                float v1 = A[m + 8][k0 + tig];
                float v2 = A[m][k0 + tig + 4];
                float v3 = A[m + 8][k0 + tig + 4];
                float h0 = tf32_rna(v0), h1 = tf32_rna(v1);
                float h2 = tf32_rna(v2), h3 = tf32_rna(v3);
                aH[mf][0] = __float_as_uint(h0); aL[mf][0] = __float_as_uint(tf32_rna(v0 - h0));
                aH[mf][1] = __float_as_uint(h1); aL[mf][1] = __float_as_uint(tf32_rna(v1 - h1));
                aH[mf][2] = __float_as_uint(h2); aL[mf][2] = __float_as_uint(tf32_rna(v2 - h2));
                aH[mf][3] = __float_as_uint(h3); aL[mf][3] = __float_as_uint(tf32_rna(v3 - h3));
            }
#pragma unroll
            for (int nf = 0; nf < 4; nf++) {
                int nn = wn * 32 + nf * 8 + gid;
                float w0 = B[k0 + tig][nn];
                float w1 = B[k0 + tig + 4][nn];
                float bh0f = tf32_rna(w0), bh1f = tf32_rna(w1);
                uint32_t bh0 = __float_as_uint(bh0f);
                uint32_t bh1 = __float_as_uint(bh1f);
                uint32_t bl0 = __float_as_uint(tf32_rna(w0 - bh0f));
                uint32_t bl1 = __float_as_uint(tf32_rna(w1 - bh1f));
#pragma unroll
                for (int mf = 0; mf < 4; mf++) {
                    mma_tf32(d[mf][nf], aH[mf][0], aH[mf][1], aH[mf][2], aH[mf][3], bl0, bl1);
                    mma_tf32(d[mf][nf], aL[mf][0], aL[mf][1], aL[mf][2], aL[mf][3], bh0, bh1);
                    mma_tf32(d[mf][nf], aH[mf][0], aH[mf][1], aH[mf][2], aH[mf][3], bh0, bh1);
                }
            }
        }
        buf ^= 1;
    }

#pragma unroll
    for (int mf = 0; mf < 4; mf++) {
        int rA = row0 + wm * 64 + mf * 16 + gid;
#pragma unroll
        for (int nf = 0; nf < 4; nf++) {
            int cA = col0 + wn * 32 + nf * 8 + tig * 2;
            *(float2*)(g_Z + (size_t)rA * 512 + cA)       = make_float2(d[mf][nf][0], d[mf][nf][1]);
            *(float2*)(g_Z + (size_t)(rA + 8) * 512 + cA) = make_float2(d[mf][nf][2], d[mf][nf][3]);
        }
    }
}

// ---------------------------------------------------------------------------
// K4: exact score = Z[row] . rh + ls + rs. One warp per candidate row.
__global__ __launch_bounds__(256) void rescore_dot_kernel(
    const float* __restrict__ chart_h, const float* __restrict__ chart_s) {
    int nrows = g_nrows;
    int row = blockIdx.x * 8 + (threadIdx.x >> 5);
    if (row >= nrows) return;
    int lane = threadIdx.x & 31;

    int code = g_rows[row];
    int bl = code >> 6, z = code & 63;
    int n = z >> 2, kl = (z >> 1) & 1, kr = z & 1;
    int b = bl / LPOS, l = bl % LPOS;
    int lcell = g_li[(l << 4) + n];
    int rcell = g_ri[(l << 4) + n];

    const float4* zp = (const float4*)(g_Z + (size_t)row * 512);
    const float4* rh = (const float4*)(chart_h + (((size_t)(kr * BATCH + b)) * NCELLS + rcell) * SIZE);
    float a = 0.f;
#pragma unroll
    for (int it = 0; it < 4; it++) {
        int i = lane + it * 32;
        float4 x = zp[i], y = rh[i];
        a += x.x*y.x + x.y*y.y + x.z*y.z + x.w*y.w;
    }
#pragma unroll
    for (int o = 16; o; o >>= 1) a += __shfl_xor_sync(0xffffffffu, a, o);
    if (lane == 0) {
        float ls = chart_s[(size_t)(kl * BATCH + b) * NCELLS + lcell];
        float rs = chart_s[(size_t)(kr * BATCH + b) * NCELLS + rcell];
        g_sexact[row] = a + ls + rs;
    }
}

// ---------------------------------------------------------------------------
// K5: per cell select exact top-2; write outputs + g_sel (all cells).
__global__ __launch_bounds__(256) void fix_select_kernel(float* __restrict__ out) {
    int bl = blockIdx.x * 256 + threadIdx.x;
    if (bl >= NCELLS_BL) return;
    int base = g_cellbase[bl];
    int cnt  = g_cellcnt[bl];

    float s1 = -INFINITY, s2 = -INFINITY;
    int z1 = 64, z2 = 64;
    for (int c = 0; c < cnt; c++) {
        float v = g_sexact[base + c];
        int z = g_rows[base + c] & 63;
        if (v > s1 || (v == s1 && z < z1)) {
            s2 = s1; z2 = z1; s1 = v; z1 = z;
        } else if (v > s2 || (v == s2 && z < z2)) {
            s2 = v; z2 = z;
        }
    }
    int o = bl * 2;
    out[OFF_S  + o]     = s1;
    out[OFF_S  + o + 1] = s2;
    out[OFF_N  + o]     = (float)(z1 >> 2);
    out[OFF_N  + o + 1] = (float)(z2 >> 2);
    out[OFF_LK + o]     = (float)((z1 >> 1) & 1);
    out[OFF_LK + o + 1] = (float)((z2 >> 1) & 1);
    out[OFF_RK + o]     = (float)(z1 & 1);
    out[OFF_RK + o + 1] = (float)(z2 & 1);
    g_sel[o]     = make_int4(z1 >> 2, (z1 >> 1) & 1, z1 & 1, 0);
    g_sel[o + 1] = make_int4(z2 >> 2, (z2 >> 1) & 1, z2 & 1, 0);
}

// ---------------------------------------------------------------------------
// K6: compose GEMM, 1x tf32, LDSM fragments, split-K=4 -> partials g_P.
__global__ __launch_bounds__(256, 2) void gemm2_mma_kernel(
    const float* __restrict__ chart_h) {
    __shared__ float sA[2][128][TPAD];
    __shared__ float sB[2][128][TPAD];
    __shared__ const float* Arow[128];

    int tid  = threadIdx.x;
    int row0 = blockIdx.y * 128;
    int col0 = blockIdx.x * 128;
    int ks   = blockIdx.z;
    int kbase = ks * 256;

    if (tid < 128) {
        int r = row0 + tid;
        int bl = r >> 1;
        int b = bl / LPOS, l = bl % LPOS;
        int4 sel = g_sel[r];
        const float* base;
        if (kbase < 512) {
            int lcell = g_li[(l << 4) + sel.x];
            base = chart_h + (((size_t)(sel.y * BATCH + b)) * NCELLS + lcell) * SIZE + kbase;
        } else {
            int rcell = g_ri[(l << 4) + sel.x];
            base = chart_h + (((size_t)(sel.z * BATCH + b)) * NCELLS + rcell) * SIZE + (kbase - 512);
        }
        Arow[tid] = base;
    }
    __syncthreads();

    int cr = tid >> 1, cw = (tid & 1) * 8;
    const float* gA = Arow[cr] + cw;
    const float* gB = g_WcT + (size_t)(col0 + cr) * 1024 + kbase + cw;

    uint32_t aBase = (uint32_t)__cvta_generic_to_shared(&sA[0][0][0]);
    uint32_t bBase = (uint32_t)__cvta_generic_to_shared(&sB[0][0][0]);
    uint32_t dA = aBase + (cr * TPAD + cw) * 4;
    uint32_t dB = bBase + (cr * TPAD + cw) * 4;

    int wid = tid >> 5, lane = tid & 31;
    int wm = wid >> 2, wn = wid & 3;
    int gid = lane >> 2, tig = lane & 3;
    int t4 = lane >> 3, lr = lane & 7;

    uint32_t aAddr[4], bAddr[2];
    {
        int arow_off = (t4 & 1) * 8 + lr, acol = (t4 >> 1) * 4;
        int brow_off = ((t4 >> 1) * 8) + lr, bcol = (t4 & 1) * 4;
#pragma unroll
        for (int mf = 0; mf < 4; mf++)
            aAddr[mf] = aBase + ((wm * 64 + mf * 16 + arow_off) * TPAD + acol) * 4;
#pragma unroll
        for (int p = 0; p < 2; p++)
            bAddr[p] = bBase + ((wn * 32 + p * 16 + brow_off) * TPAD + bcol) * 4;
    }

    float d[4][4][4];
#pragma unroll
    for (int mf = 0; mf < 4; mf++)
#pragma unroll
        for (int nf = 0; nf < 4; nf++)
#pragma unroll
            for (int c = 0; c < 4; c++) d[mf][nf][c] = 0.f;

    CP_ASYNC16(dA, gA);
    CP_ASYNC16(dA + 16, gA + 4);
    CP_ASYNC16(dB, gB);
    CP_ASYNC16(dB + 16, gB + 4);
    CP_COMMIT();

    int buf = 0;
    for (int kt = 0; kt < 16; kt++) {
        CP_WAIT0();
        __syncthreads();
        if (kt < 15) {
            int nb = buf ^ 1;
            size_t go = (size_t)(kt + 1) * 16;
            uint32_t nA = dA + nb * TBUF_BYTES;
            uint32_t nB = dB + nb * TBUF_BYTES;
            CP_ASYNC16(nA, gA + go);
            CP_ASYNC16(nA + 16, gA + go + 4);
            CP_ASYNC16(nB, gB + go);
            CP_ASYNC16(nB + 16, gB + go + 4);
            CP_COMMIT();
        }

        uint32_t boff = buf * TBUF_BYTES;
#pragma unroll
        for (int kf = 0; kf < 2; kf++) {
            uint32_t koff = boff + kf * 32;
            uint32_t a[4][4], bb[4][2];
#pragma unroll
            for (int mf = 0; mf < 4; mf++)
                LDSM4(a[mf][0], a[mf][1], a[mf][2], a[mf][3], aAddr[mf] + koff);
#pragma unroll
            for (int p = 0; p < 2; p++)
                LDSM4(bb[2 * p][0], bb[2 * p][1], bb[2 * p + 1][0], bb[2 * p + 1][1],
                      bAddr[p] + koff);
#pragma unroll
            for (int nf = 0; nf < 4; nf++)
#pragma unroll
                for (int mf = 0; mf < 4; mf++)
                    mma_tf32(d[mf][nf], a[mf][0], a[mf][1], a[mf][2], a[mf][3],
                             bb[nf][0], bb[nf][1]);
        }
        buf ^= 1;
    }

#pragma unroll
    for (int mf = 0; mf < 4; mf++) {
        int rA = row0 + wm * 64 + mf * 16 + gid;
#pragma unroll
        for (int nf = 0; nf < 4; nf++) {
            int cA = col0 + wn * 32 + nf * 8 + tig * 2;
            float* p = g_P + ((size_t)ks * ROWS2 + rA) * 512 + cA;
            *(float2*)p                = make_float2(d[mf][nf][0], d[mf][nf][1]);
            *(float2*)(p + 8 * 512)    = make_float2(d[mf][nf][2], d[mf][nf][3]);
        }
    }
}

// ---------------------------------------------------------------------------
// K7: combine split-K partials + bias + tanh + unit-norm, write topk_h.
__global__ __launch_bounds__(256) void combine_normalize_kernel(
    const float* __restrict__ bc, float* __restrict__ out) {
    int r = blockIdx.x;
    int t = threadIdx.x;
    const float* p = g_P + (size_t)r * 512;
    const size_t stride = (size_t)ROWS2 * 512;

    float v0 = bc[t]       + p[t]       + p[t + stride]       + p[t + 2*stride]       + p[t + 3*stride];
    float v1 = bc[t + 256] + p[t + 256] + p[t + 256 + stride] + p[t + 256 + 2*stride] + p[t + 256 + 3*stride];
    v0 = tanhf(v0);
    v1 = tanhf(v1);

    float ss = v0 * v0 + v1 * v1;
#pragma unroll
    for (int o = 16; o; o >>= 1) ss += __shfl_xor_sync(0xffffffffu, ss, o);
    __shared__ float red[8];
    __shared__ float s_inv;
    if ((t & 31) == 0) red[t >> 5] = ss;
    __syncthreads();
    if (t == 0) {
        float x = 0.f;
#pragma unroll
        for (int i = 0; i < 8; i++) x += red[i];
        s_inv = 1.0f / sqrtf(x);
    }
    __syncthreads();
    float inv = s_inv;
    out[OFF_H + (size_t)r * 512 + t]       = v0 * inv;
    out[OFF_H + (size_t)r * 512 + t + 256] = v1 * inv;
}

// ---------------------------------------------------------------------------
extern "C" void kernel_launch(void* const* d_in, const int* in_sizes, int n_in,
                              void* d_out, int out_size) {
    const float* chart_h = (const float*)d_in[0];
    const float* chart_s = (const float*)d_in[1];
    const void*  l_index = d_in[2];
    const void*  r_index = d_in[3];
    const float* mat     = (const float*)d_in[4];
    const float* Wc      = (const float*)d_in[5];
    const float* bc      = (const float*)d_in[6];
    float* out = (float*)d_out;

    float* matT; cudaGetSymbolAddress((void**)&matT, g_matT);
    float* WcT;  cudaGetSymbolAddress((void**)&WcT,  g_WcT);

    conv_idx_kernel<<<3, 256>>>(l_index, r_index);
    transpose_kernel<<<dim3(16, 16), dim3(32, 8)>>>(mat, matT, 512, 512);
    transpose_kernel<<<dim3(16, 32), dim3(32, 8)>>>(Wc, WcT, 1024, 512);
    gemm1_mma_kernel<<<dim3(4, ROWS1 / 128), 256>>>(chart_h);
    score_topk_kernel<<<NCELLS_BL, 256>>>(chart_h, chart_s);
    rescore_gemm_kernel<<<dim3(4, MAXR / 128), 256>>>(chart_h, mat);
    rescore_dot_kernel<<<MAXR / 8, 256>>>(chart_h, chart_s);
    fix_select_kernel<<<6, 256>>>(out);
    gemm2_mma_kernel<<<dim3(4, ROWS2 / 128, KSPLIT), 256>>>(chart_h);
    combine_normalize_kernel<<<ROWS2, 256>>>(bc, out);
}

// round 9
// speedup vs baseline: 2.9014x; 1.0186x over previous
#include <cuda_runtime.h>
#include <math.h>
#include <stdint.h>

// Problem constants
#define LEVEL   16
#define LENGTH  64
#define TOPK    2
#define SIZE    512
#define BATCH   32
#define NEG     (-1e8f)

#define LPOS    48              // LENGTH - LEVEL
#define NCELLS  904
#define NIDX    768             // LPOS * LEVEL
#define ROWS1   49152           // K*B*LPOS*LEVEL  (GEMM1 rows)
#define ROWS2   3072            // B*LPOS*K        (GEMM2 rows)
#define KSPLIT  4
#define NCELLS_BL 1536          // BATCH*LPOS
#define MAXCAND 12
#define MAXR    (NCELLS_BL * MAXCAND)   // 18432
#define GUARD   0.12f

// Output layout (float32, concatenated in reference return order)
#define OFF_H   0
#define OFF_S   1572864         // 3072*512
#define OFF_N   1575936
#define OFF_LK  1579008
#define OFF_RK  1582080

// smem geometry: rescore kernel (round-7 layout)
#define A_PAD   20
#define B_PAD   136
#define A_BUF   (128 * A_PAD)
#define B_BUF   (16 * B_PAD)
// smem geometry: LDSM kernels, 4-stage pipeline
#define TPAD    20
#define NST     4
#define ABYTES  (128 * TPAD * 4)            // 10240
#define STAGE_BYTES (2 * ABYTES)            // 20480 (A then B)
#define SMEM_PIPE (NST * STAGE_BYTES)       // 81920

// Scratch (static device globals: allocation-free per harness rules)
__device__ float g_U[(size_t)ROWS1 * 512];              // ~100.7 MB approx U
__device__ float g_Z[(size_t)MAXR * 512];               // ~37.7 MB rescore Z
__device__ float g_P[(size_t)KSPLIT * ROWS2 * 512];     // ~25 MB split-K partials
__device__ float g_matT[512 * 512];                     // mat^T [n][k]
__device__ float g_WcT[512 * 1024];                     // Wc^T  [n][k]
__device__ int   g_li[NIDX];
__device__ int   g_ri[NIDX];
__device__ int4  g_sel[ROWS2];
__device__ int   g_nrows;
__device__ int   g_rows[MAXR];          // (bl<<6)|z
__device__ float g_sexact[MAXR];
__device__ int   g_cellbase[NCELLS_BL];
__device__ int   g_cellcnt[NCELLS_BL];

#define CP_ASYNC16(dst32, src) \
    asm volatile("cp.async.cg.shared.global [%0], [%1], 16;" :: "r"(dst32), "l"(src))
#define CP_COMMIT()  asm volatile("cp.async.commit_group;")
#define CP_WAIT0()   asm volatile("cp.async.wait_group 0;")
#define CP_WAIT2()   asm volatile("cp.async.wait_group 2;")

#define LDSM4(r0, r1, r2, r3, a) \
    asm volatile("ldmatrix.sync.aligned.m8n8.x4.shared.b16 {%0,%1,%2,%3}, [%4];" \
        : "=r"(r0), "=r"(r1), "=r"(r2), "=r"(r3) : "r"(a))

__device__ __forceinline__ void mma_tf32(float d[4],
        uint32_t a0, uint32_t a1, uint32_t a2, uint32_t a3,
        uint32_t b0, uint32_t b1) {
    asm volatile(
        "mma.sync.aligned.m16n8k8.row.col.f32.tf32.tf32.f32 "
        "{%0,%1,%2,%3}, {%4,%5,%6,%7}, {%8,%9}, {%0,%1,%2,%3};"
        : "+f"(d[0]), "+f"(d[1]), "+f"(d[2]), "+f"(d[3])
        : "r"(a0), "r"(a1), "r"(a2), "r"(a3), "r"(b0), "r"(b1));
}

__device__ __forceinline__ float tf32_rna(float x) {
    uint32_t u;
    asm("cvt.rna.tf32.f32 %0, %1;" : "=r"(u) : "f"(x));
    return __uint_as_float(u);
}

// ---------------------------------------------------------------------------
// K0: index conversion + counter reset.
__global__ void conv_idx_kernel(const void* __restrict__ lraw,
                                const void* __restrict__ rraw) {
    if (blockIdx.x == 0 && threadIdx.x == 0) g_nrows = 0;
    const int* w = (const int*)lraw;
    bool is64 = (w[1] == 0 && w[2] == 64);
    int t = blockIdx.x * blockDim.x + threadIdx.x;
    if (t < NIDX) {
        if (is64) {
            g_li[t] = (int)((const long long*)lraw)[t];
            g_ri[t] = (int)((const long long*)rraw)[t];
        } else {
            g_li[t] = ((const int*)lraw)[t];
            g_ri[t] = ((const int*)rraw)[t];
        }
    }
}

// ---------------------------------------------------------------------------
// K0b: tiled transpose, dst[c][r] = src[r][c].  block (32,8).
__global__ void transpose_kernel(const float* __restrict__ src,
                                 float* __restrict__ dst, int rows, int cols) {
    __shared__ float tile[32][33];
    int bx = blockIdx.x * 32;
    int by = blockIdx.y * 32;
    int tx = threadIdx.x, ty = threadIdx.y;
#pragma unroll
    for (int i = 0; i < 32; i += 8)
        tile[ty + i][tx] = src[(size_t)(by + ty + i) * cols + bx + tx];
    __syncthreads();
#pragma unroll
    for (int i = 0; i < 32; i += 8)
        dst[(size_t)(bx + ty + i) * rows + by + tx] = tile[tx][ty + i];
}

// ---------------------------------------------------------------------------
// K1: U_approx = gather(chart_h left cells) @ mat, 1x tf32, LDSM + 4-stage
// cp.async pipeline. A smem [m128][k16]p20, B smem [n128][k16]p20 (matT).
__global__ __launch_bounds__(256, 2) void gemm1_mma_kernel(
    const float* __restrict__ chart_h) {
    extern __shared__ float sm[];
    __shared__ const float* Arow[128];

    int tid  = threadIdx.x;
    int row0 = blockIdx.y * 128;
    int col0 = blockIdx.x * 128;

    if (tid < 128) {
        int r = row0 + tid;
        int k = r & 1;
        int t = r >> 1;
        int n = t & 15;
        int bl = t >> 4;
        int l = bl % LPOS, b = bl / LPOS;
        int cell = g_li[(l << 4) + n];
        Arow[tid] = chart_h + (((size_t)(k * BATCH + b)) * NCELLS + cell) * SIZE;
    }
    __syncthreads();

    int cr = tid >> 1, cw = (tid & 1) * 8;     // copy role: row, 8-float half
    const float* gA = Arow[cr] + cw;
    const float* gB = g_matT + (size_t)(col0 + cr) * 512 + cw;

    uint32_t base = (uint32_t)__cvta_generic_to_shared(sm);
    uint32_t cpA = base + (cr * TPAD + cw) * 4;            // stage-0 A dst
    uint32_t cpB = base + ABYTES + (cr * TPAD + cw) * 4;   // stage-0 B dst

    int wid = tid >> 5, lane = tid & 31;
    int wm = wid >> 2, wn = wid & 3;
    int gid = lane >> 2, tig = lane & 3;
    int t4 = lane >> 3, lr = lane & 7;

    uint32_t aAddr[4], bAddr[2];
    {
        int arow_off = (t4 & 1) * 8 + lr, acol = (t4 >> 1) * 4;
        int brow_off = ((t4 >> 1) * 8) + lr, bcol = (t4 & 1) * 4;
#pragma unroll
        for (int mf = 0; mf < 4; mf++)
            aAddr[mf] = base + ((wm * 64 + mf * 16 + arow_off) * TPAD + acol) * 4;
#pragma unroll
        for (int p = 0; p < 2; p++)
            bAddr[p] = base + ABYTES + ((wn * 32 + p * 16 + brow_off) * TPAD + bcol) * 4;
    }

    float d[4][4][4];
#pragma unroll
    for (int mf = 0; mf < 4; mf++)
#pragma unroll
        for (int nf = 0; nf < 4; nf++)
#pragma unroll
            for (int c = 0; c < 4; c++) d[mf][nf][c] = 0.f;

    // prologue: fill stages 0..NST-2
#pragma unroll
    for (int s = 0; s < NST - 1; s++) {
        uint32_t so = s * STAGE_BYTES;
        size_t go = (size_t)s * 16;
        CP_ASYNC16(cpA + so, gA + go);
        CP_ASYNC16(cpA + so + 16, gA + go + 4);
        CP_ASYNC16(cpB + so, gB + go);
        CP_ASYNC16(cpB + so + 16, gB + go + 4);
        CP_COMMIT();
    }

    for (int kt = 0; kt < 32; kt++) {
        CP_WAIT2();
        __syncthreads();
        int pf = kt + NST - 1;
        if (pf < 32) {
            uint32_t so = (pf & (NST - 1)) * STAGE_BYTES;
            size_t go = (size_t)pf * 16;
            CP_ASYNC16(cpA + so, gA + go);
            CP_ASYNC16(cpA + so + 16, gA + go + 4);
            CP_ASYNC16(cpB + so, gB + go);
            CP_ASYNC16(cpB + so + 16, gB + go + 4);
        }
        CP_COMMIT();     // commit every iter so wait_group counting stays uniform

        uint32_t soff = (kt & (NST - 1)) * STAGE_BYTES;
#pragma unroll
        for (int kf = 0; kf < 2; kf++) {
            uint32_t koff = soff + kf * 32;
            uint32_t a[4][4], bb[4][2];
#pragma unroll
            for (int mf = 0; mf < 4; mf++)
                LDSM4(a[mf][0], a[mf][1], a[mf][2], a[mf][3], aAddr[mf] + koff);
#pragma unroll
            for (int p = 0; p < 2; p++)
                LDSM4(bb[2 * p][0], bb[2 * p][1], bb[2 * p + 1][0], bb[2 * p + 1][1],
                      bAddr[p] + koff);
#pragma unroll
            for (int nf = 0; nf < 4; nf++)
#pragma unroll
                for (int mf = 0; mf < 4; mf++)
                    mma_tf32(d[mf][nf], a[mf][0], a[mf][1], a[mf][2], a[mf][3],
                             bb[nf][0], bb[nf][1]);
        }
    }

#pragma unroll
    for (int mf = 0; mf < 4; mf++) {
        int rA = row0 + wm * 64 + mf * 16 + gid;
#pragma unroll
        for (int nf = 0; nf < 4; nf++) {
            int cA = col0 + wn * 32 + nf * 8 + tig * 2;
            *(float2*)(g_U + (size_t)rA * 512 + cA)       = make_float2(d[mf][nf][0], d[mf][nf][1]);
            *(float2*)(g_U + (size_t)(rA + 8) * 512 + cA) = make_float2(d[mf][nf][2], d[mf][nf][3]);
        }
    }
}

// ---------------------------------------------------------------------------
// K2: approx scores + nomination: top-2 plus all combos within GUARD of
// approx-2nd; exact values come from the rescore pipeline.
__global__ __launch_bounds__(256) void score_topk_kernel(
    const float* __restrict__ chart_h, const float* __restrict__ chart_s) {
    int bl = blockIdx.x;
    int b = bl / LPOS, l = bl % LPOS;
    int warp = threadIdx.x >> 5;
    int lane = threadIdx.x & 31;

    __shared__ float s[64];

    for (int n = warp; n < 16; n += 8) {
        int lcell = g_li[(l << 4) + n];
        int rcell = g_ri[(l << 4) + n];
        const float4* u0 = (const float4*)(g_U + ((((size_t)bl * 16) + n) * 2 + 0) * 512);
        const float4* u1 = u0 + 128;
        const float4* r0 = (const float4*)(chart_h + (((size_t)b) * NCELLS + rcell) * SIZE);
        const float4* r1 = (const float4*)(chart_h + (((size_t)(BATCH + b)) * NCELLS + rcell) * SIZE);
        float a00 = 0.f, a01 = 0.f, a10 = 0.f, a11 = 0.f;
#pragma unroll
        for (int it = 0; it < 4; it++) {
            int i = lane + it * 32;
            float4 x0 = u0[i], x1 = u1[i], y0 = r0[i], y1 = r1[i];
            a00 += x0.x*y0.x + x0.y*y0.y + x0.z*y0.z + x0.w*y0.w;
            a01 += x0.x*y1.x + x0.y*y1.y + x0.z*y1.z + x0.w*y1.w;
            a10 += x1.x*y0.x + x1.y*y0.y + x1.z*y0.z + x1.w*y0.w;
            a11 += x1.x*y1.x + x1.y*y1.y + x1.z*y1.z + x1.w*y1.w;
        }
#pragma unroll
        for (int o = 16; o; o >>= 1) {
            a00 += __shfl_xor_sync(0xffffffffu, a00, o);
            a01 += __shfl_xor_sync(0xffffffffu, a01, o);
            a10 += __shfl_xor_sync(0xffffffffu, a10, o);
            a11 += __shfl_xor_sync(0xffffffffu, a11, o);
        }
        if (lane == 0) {
            float ls0 = chart_s[(size_t)b * NCELLS + lcell];
            float ls1 = chart_s[(size_t)(BATCH + b) * NCELLS + lcell];
            float rs0 = chart_s[(size_t)b * NCELLS + rcell];
            float rs1 = chart_s[(size_t)(BATCH + b) * NCELLS + rcell];
            float v00 = a00 + ls0 + rs0, v01 = a01 + ls0 + rs1;
            float v10 = a10 + ls1 + rs0, v11 = a11 + ls1 + rs1;
            if (n == 0) { v10 = NEG; v11 = NEG; }   // penalty: catalan(1)=1
            s[n * 4 + 0] = v00; s[n * 4 + 1] = v01;
            s[n * 4 + 2] = v10; s[n * 4 + 3] = v11;
        }
    }
    __syncthreads();

    if (threadIdx.x == 0) {
        float b1 = -INFINITY; int i1 = 0;
        for (int z = 0; z < 64; z++) { float v = s[z]; if (v > b1) { b1 = v; i1 = z; } }
        float b2 = -INFINITY; int i2 = 0;
        for (int z = 0; z < 64; z++) {
            if (z == i1) continue;
            float v = s[z]; if (v > b2) { b2 = v; i2 = z; }
        }
        int cand[MAXCAND];
        int cnt = 0;
        cand[cnt++] = i1;
        cand[cnt++] = i2;
        float thr = b2 - GUARD;
        for (int z = 0; z < 64 && cnt < MAXCAND; z++) {
            if (z == i1 || z == i2) continue;
            if (s[z] >= thr) cand[cnt++] = z;
        }
        int base = atomicAdd(&g_nrows, cnt);
        g_cellbase[bl] = base;
        g_cellcnt[bl]  = cnt;
        for (int c = 0; c < cnt; c++) g_rows[base + c] = (bl << 6) | cand[c];
    }
}

// ---------------------------------------------------------------------------
// K3: 3xTF32 rescore GEMM: Z = lh_cand @ mat (fp32-grade), in-fragment split.
__global__ __launch_bounds__(256, 2) void rescore_gemm_kernel(
    const float* __restrict__ chart_h, const float* __restrict__ mat) {
    int nrows = g_nrows;
    if ((int)(blockIdx.y * 128) >= nrows) return;

    __shared__ float sA[2][128][A_PAD];
    __shared__ float sB[2][16][B_PAD];
    __shared__ const float* Arow[128];

    int tid  = threadIdx.x;
    int row0 = blockIdx.y * 128;
    int col0 = blockIdx.x * 128;

    if (tid < 128) {
        int r = row0 + tid;
        const float* p = chart_h;
        if (r < nrows) {
            int code = g_rows[r];
            int bl = code >> 6, z = code & 63;
            int n = z >> 2, kl = (z >> 1) & 1;
            int b = bl / LPOS, l = bl % LPOS;
            int lcell = g_li[(l << 4) + n];
            p = chart_h + (((size_t)(kl * BATCH + b)) * NCELLS + lcell) * SIZE;
        }
        Arow[tid] = p;
    }
    __syncthreads();

    int ar = tid >> 1,  aw = (tid & 1) * 8;
    int brr = tid >> 4, bw = (tid & 15) * 8;
    const float* gA = Arow[ar] + aw;
    const float* gB = mat + (size_t)brr * 512 + col0 + bw;

    uint32_t dA = (uint32_t)__cvta_generic_to_shared(&sA[0][ar][aw]);
    uint32_t dB = (uint32_t)__cvta_generic_to_shared(&sB[0][brr][bw]);

    int wid = tid >> 5, lane = tid & 31;
    int wm = wid >> 2, wn = wid & 3;
    int gid = lane >> 2, tig = lane & 3;

    float d[4][4][4];
#pragma unroll
    for (int mf = 0; mf < 4; mf++)
#pragma unroll
        for (int nf = 0; nf < 4; nf++)
#pragma unroll
            for (int c = 0; c < 4; c++) d[mf][nf][c] = 0.f;

    CP_ASYNC16(dA, gA);
    CP_ASYNC16(dA + 16, gA + 4);
    CP_ASYNC16(dB, gB);
    CP_ASYNC16(dB + 16, gB + 4);
    CP_COMMIT();

    int buf = 0;
    for (int kt = 0; kt < 32; kt++) {
        CP_WAIT0();
        __syncthreads();
        if (kt < 31) {
            int nb = buf ^ 1;
            size_t goA = (size_t)(kt + 1) * 16;
            size_t goB = (size_t)(kt + 1) * 16 * 512;
            uint32_t nA = dA + (nb ? A_BUF * 4 : 0) - (buf ? A_BUF * 4 : 0);
            uint32_t nB = dB + (nb ? B_BUF * 4 : 0) - (buf ? B_BUF * 4 : 0);
            CP_ASYNC16(nA, gA + goA);
            CP_ASYNC16(nA + 16, gA + goA + 4);
            CP_ASYNC16(nB, gB + goB);
            CP_ASYNC16(nB + 16, gB + goB + 4);
            CP_COMMIT();
            dA = nA; dB = nB;
        }

        const float (*A)[A_PAD] = sA[buf];
        const float (*B)[B_PAD] = sB[buf];
#pragma unroll
        for (int kf = 0; kf < 2; kf++) {
            int k0 = kf * 8;
            uint32_t aH[4][4], aL[4][4];
#pragma unroll
            for (int mf = 0; mf < 4; mf++) {
                int m = wm * 64 + mf * 16 + gid;
                float v0 = A[m][k0 + tig];
                float v1 = A[m + 8][k0 + tig];
                float v2 = A[m][k0 + tig + 4];
                float v3 = A[m + 8][k0 + tig + 4];
                float h0 = tf32_rna(v0), h1 = tf32_rna(v1);
                float h2 = tf32_rna(v2), h3 = tf32_rna(v3);
                aH[mf][0] = __float_as_uint(h0); aL[mf][0] = __float_as_uint(tf32_rna(v0 - h0));
                aH[mf][1] = __float_as_uint(h1); aL[mf][1] = __float_as_uint(tf32_rna(v1 - h1));
                aH[mf][2] = __float_as_uint(h2); aL[mf][2] = __float_as_uint(tf32_rna(v2 - h2));
                aH[mf][3] = __float_as_uint(h3); aL[mf][3] = __float_as_uint(tf32_rna(v3 - h3));
            }
#pragma unroll
            for (int nf = 0; nf < 4; nf++) {
                int nn = wn * 32 + nf * 8 + gid;
                float w0 = B[k0 + tig][nn];
                float w1 = B[k0 + tig + 4][nn];
                float bh0f = tf32_rna(w0), bh1f = tf32_rna(w1);
                uint32_t bh0 = __float_as_uint(bh0f);
                uint32_t bh1 = __float_as_uint(bh1f);
                uint32_t bl0 = __float_as_uint(tf32_rna(w0 - bh0f));
                uint32_t bl1 = __float_as_uint(tf32_rna(w1 - bh1f));
#pragma unroll
                for (int mf = 0; mf < 4; mf++) {
                    mma_tf32(d[mf][nf], aH[mf][0], aH[mf][1], aH[mf][2], aH[mf][3], bl0, bl1);
                    mma_tf32(d[mf][nf], aL[mf][0], aL[mf][1], aL[mf][2], aL[mf][3], bh0, bh1);
                    mma_tf32(d[mf][nf], aH[mf][0], aH[mf][1], aH[mf][2], aH[mf][3], bh0, bh1);
                }
            }
        }
        buf ^= 1;
    }

#pragma unroll
    for (int mf = 0; mf < 4; mf++) {
        int rA = row0 + wm * 64 + mf * 16 + gid;
#pragma unroll
        for (int nf = 0; nf < 4; nf++) {
            int cA = col0 + wn * 32 + nf * 8 + tig * 2;
            *(float2*)(g_Z + (size_t)rA * 512 + cA)       = make_float2(d[mf][nf][0], d[mf][nf][1]);
            *(float2*)(g_Z + (size_t)(rA + 8) * 512 + cA) = make_float2(d[mf][nf][2], d[mf][nf][3]);
        }
    }
}

// ---------------------------------------------------------------------------
// K4: exact score = Z[row] . rh + ls + rs. One warp per candidate row.
__global__ __launch_bounds__(256) void rescore_dot_kernel(
    const float* __restrict__ chart_h, const float* __restrict__ chart_s) {
    int nrows = g_nrows;
    int row = blockIdx.x * 8 + (threadIdx.x >> 5);
    if (row >= nrows) return;
    int lane = threadIdx.x & 31;

    int code = g_rows[row];
    int bl = code >> 6, z = code & 63;
    int n = z >> 2, kl = (z >> 1) & 1, kr = z & 1;
    int b = bl / LPOS, l = bl % LPOS;
    int lcell = g_li[(l << 4) + n];
    int rcell = g_ri[(l << 4) + n];

    const float4* zp = (const float4*)(g_Z + (size_t)row * 512);
    const float4* rh = (const float4*)(chart_h + (((size_t)(kr * BATCH + b)) * NCELLS + rcell) * SIZE);
    float a = 0.f;
#pragma unroll
    for (int it = 0; it < 4; it++) {
        int i = lane + it * 32;
        float4 x = zp[i], y = rh[i];
        a += x.x*y.x + x.y*y.y + x.z*y.z + x.w*y.w;
    }
#pragma unroll
    for (int o = 16; o; o >>= 1) a += __shfl_xor_sync(0xffffffffu, a, o);
    if (lane == 0) {
        float ls = chart_s[(size_t)(kl * BATCH + b) * NCELLS + lcell];
        float rs = chart_s[(size_t)(kr * BATCH + b) * NCELLS + rcell];
        g_sexact[row] = a + ls + rs;
    }
}

// ---------------------------------------------------------------------------
// K5: per cell select exact top-2; write outputs + g_sel (all cells).
__global__ __launch_bounds__(256) void fix_select_kernel(float* __restrict__ out) {
    int bl = blockIdx.x * 256 + threadIdx.x;
    if (bl >= NCELLS_BL) return;
    int base = g_cellbase[bl];
    int cnt  = g_cellcnt[bl];

    float s1 = -INFINITY, s2 = -INFINITY;
    int z1 = 64, z2 = 64;
    for (int c = 0; c < cnt; c++) {
        float v = g_sexact[base + c];
        int z = g_rows[base + c] & 63;
        if (v > s1 || (v == s1 && z < z1)) {
            s2 = s1; z2 = z1; s1 = v; z1 = z;
        } else if (v > s2 || (v == s2 && z < z2)) {
            s2 = v; z2 = z;
        }
    }
    int o = bl * 2;
    out[OFF_S  + o]     = s1;
    out[OFF_S  + o + 1] = s2;
    out[OFF_N  + o]     = (float)(z1 >> 2);
    out[OFF_N  + o + 1] = (float)(z2 >> 2);
    out[OFF_LK + o]     = (float)((z1 >> 1) & 1);
    out[OFF_LK + o + 1] = (float)((z2 >> 1) & 1);
    out[OFF_RK + o]     = (float)(z1 & 1);
    out[OFF_RK + o + 1] = (float)(z2 & 1);
    g_sel[o]     = make_int4(z1 >> 2, (z1 >> 1) & 1, z1 & 1, 0);
    g_sel[o + 1] = make_int4(z2 >> 2, (z2 >> 1) & 1, z2 & 1, 0);
}

// ---------------------------------------------------------------------------
// K6: compose GEMM, 1x tf32, LDSM + 4-stage pipeline, split-K=4 -> g_P.
__global__ __launch_bounds__(256, 2) void gemm2_mma_kernel(
    const float* __restrict__ chart_h) {
    extern __shared__ float sm[];
    __shared__ const float* Arow[128];

    int tid  = threadIdx.x;
    int row0 = blockIdx.y * 128;
    int col0 = blockIdx.x * 128;
    int ks   = blockIdx.z;
    int kbase = ks * 256;

    if (tid < 128) {
        int r = row0 + tid;
        int bl = r >> 1;
        int b = bl / LPOS, l = bl % LPOS;
        int4 sel = g_sel[r];
        const float* base;
        if (kbase < 512) {
            int lcell = g_li[(l << 4) + sel.x];
            base = chart_h + (((size_t)(sel.y * BATCH + b)) * NCELLS + lcell) * SIZE + kbase;
        } else {
            int rcell = g_ri[(l << 4) + sel.x];
            base = chart_h + (((size_t)(sel.z * BATCH + b)) * NCELLS + rcell) * SIZE + (kbase - 512);
        }
        Arow[tid] = base;
    }
    __syncthreads();

    int cr = tid >> 1, cw = (tid & 1) * 8;
    const float* gA = Arow[cr] + cw;
    const float* gB = g_WcT + (size_t)(col0 + cr) * 1024 + kbase + cw;

    uint32_t base = (uint32_t)__cvta_generic_to_shared(sm);
    uint32_t cpA = base + (cr * TPAD + cw) * 4;
    uint32_t cpB = base + ABYTES + (cr * TPAD + cw) * 4;

    int wid = tid >> 5, lane = tid & 31;
    int wm = wid >> 2, wn = wid & 3;
    int gid = lane >> 2, tig = lane & 3;
    int t4 = lane >> 3, lr = lane & 7;

    uint32_t aAddr[4], bAddr[2];
    {
        int arow_off = (t4 & 1) * 8 + lr, acol = (t4 >> 1) * 4;
        int brow_off = ((t4 >> 1) * 8) + lr, bcol = (t4 & 1) * 4;
#pragma unroll
        for (int mf = 0; mf < 4; mf++)
            aAddr[mf] = base + ((wm * 64 + mf * 16 + arow_off) * TPAD + acol) * 4;
#pragma unroll
        for (int p = 0; p < 2; p++)
            bAddr[p] = base + ABYTES + ((wn * 32 + p * 16 + brow_off) * TPAD + bcol) * 4;
    }

    float d[4][4][4];
#pragma unroll
    for (int mf = 0; mf < 4; mf++)
#pragma unroll
        for (int nf = 0; nf < 4; nf++)
#pragma unroll
            for (int c = 0; c < 4; c++) d[mf][nf][c] = 0.f;

#pragma unroll
    for (int s = 0; s < NST - 1; s++) {
        uint32_t so = s * STAGE_BYTES;
        size_t go = (size_t)s * 16;
        CP_ASYNC16(cpA + so, gA + go);
        CP_ASYNC16(cpA + so + 16, gA + go + 4);
        CP_ASYNC16(cpB + so, gB + go);
        CP_ASYNC16(cpB + so + 16, gB + go + 4);
        CP_COMMIT();
    }

    for (int kt = 0; kt < 16; kt++) {
        CP_WAIT2();
        __syncthreads();
        int pf = kt + NST - 1;
        if (pf < 16) {
            uint32_t so = (pf & (NST - 1)) * STAGE_BYTES;
            size_t go = (size_t)pf * 16;
            CP_ASYNC16(cpA + so, gA + go);
            CP_ASYNC16(cpA + so + 16, gA + go + 4);
            CP_ASYNC16(cpB + so, gB + go);
            CP_ASYNC16(cpB + so + 16, gB + go + 4);
        }
        CP_COMMIT();

        uint32_t soff = (kt & (NST - 1)) * STAGE_BYTES;
#pragma unroll
        for (int kf = 0; kf < 2; kf++) {
            uint32_t koff = soff + kf * 32;
            uint32_t a[4][4], bb[4][2];
#pragma unroll
            for (int mf = 0; mf < 4; mf++)
                LDSM4(a[mf][0], a[mf][1], a[mf][2], a[mf][3], aAddr[mf] + koff);
#pragma unroll
            for (int p = 0; p < 2; p++)
                LDSM4(bb[2 * p][0], bb[2 * p][1], bb[2 * p + 1][0], bb[2 * p + 1][1],
                      bAddr[p] + koff);
#pragma unroll
            for (int nf = 0; nf < 4; nf++)
#pragma unroll
                for (int mf = 0; mf < 4; mf++)
                    mma_tf32(d[mf][nf], a[mf][0], a[mf][1], a[mf][2], a[mf][3],
                             bb[nf][0], bb[nf][1]);
        }
    }

#pragma unroll
    for (int mf = 0; mf < 4; mf++) {
        int rA = row0 + wm * 64 + mf * 16 + gid;
#pragma unroll
        for (int nf = 0; nf < 4; nf++) {
            int cA = col0 + wn * 32 + nf * 8 + tig * 2;
            float* p = g_P + ((size_t)ks * ROWS2 + rA) * 512 + cA;
            *(float2*)p                = make_float2(d[mf][nf][0], d[mf][nf][1]);
            *(float2*)(p + 8 * 512)    = make_float2(d[mf][nf][2], d[mf][nf][3]);
        }
    }
}

// ---------------------------------------------------------------------------
// K7: combine split-K partials + bias + tanh + unit-norm, write topk_h.
__global__ __launch_bounds__(256) void combine_normalize_kernel(
    const float* __restrict__ bc, float* __restrict__ out) {
    int r = blockIdx.x;
    int t = threadIdx.x;
    const float* p = g_P + (size_t)r * 512;
    const size_t stride = (size_t)ROWS2 * 512;

    float v0 = bc[t]       + p[t]       + p[t + stride]       + p[t + 2*stride]       + p[t + 3*stride];
    float v1 = bc[t + 256] + p[t + 256] + p[t + 256 + stride] + p[t + 256 + 2*stride] + p[t + 256 + 3*stride];
    v0 = tanhf(v0);
    v1 = tanhf(v1);

    float ss = v0 * v0 + v1 * v1;
#pragma unroll
    for (int o = 16; o; o >>= 1) ss += __shfl_xor_sync(0xffffffffu, ss, o);
    __shared__ float red[8];
    __shared__ float s_inv;
    if ((t & 31) == 0) red[t >> 5] = ss;
    __syncthreads();
    if (t == 0) {
        float x = 0.f;
#pragma unroll
        for (int i = 0; i < 8; i++) x += red[i];
        s_inv = 1.0f / sqrtf(x);
    }
    __syncthreads();
    float inv = s_inv;
    out[OFF_H + (size_t)r * 512 + t]       = v0 * inv;
    out[OFF_H + (size_t)r * 512 + t + 256] = v1 * inv;
}

// ---------------------------------------------------------------------------
extern "C" void kernel_launch(void* const* d_in, const int* in_sizes, int n_in,
                              void* d_out, int out_size) {
    const float* chart_h = (const float*)d_in[0];
    const float* chart_s = (const float*)d_in[1];
    const void*  l_index = d_in[2];
    const void*  r_index = d_in[3];
    const float* mat     = (const float*)d_in[4];
    const float* Wc      = (const float*)d_in[5];
    const float* bc      = (const float*)d_in[6];
    float* out = (float*)d_out;

    float* matT; cudaGetSymbolAddress((void**)&matT, g_matT);
    float* WcT;  cudaGetSymbolAddress((void**)&WcT,  g_WcT);

    cudaFuncSetAttribute(gemm1_mma_kernel,
                         cudaFuncAttributeMaxDynamicSharedMemorySize, SMEM_PIPE);
    cudaFuncSetAttribute(gemm2_mma_kernel,
                         cudaFuncAttributeMaxDynamicSharedMemorySize, SMEM_PIPE);

    conv_idx_kernel<<<3, 256>>>(l_index, r_index);
    transpose_kernel<<<dim3(16, 16), dim3(32, 8)>>>(mat, matT, 512, 512);
    transpose_kernel<<<dim3(16, 32), dim3(32, 8)>>>(Wc, WcT, 1024, 512);
    gemm1_mma_kernel<<<dim3(4, ROWS1 / 128), 256, SMEM_PIPE>>>(chart_h);
    score_topk_kernel<<<NCELLS_BL, 256>>>(chart_h, chart_s);
    rescore_gemm_kernel<<<dim3(4, MAXR / 128), 256>>>(chart_h, mat);
    rescore_dot_kernel<<<MAXR / 8, 256>>>(chart_h, chart_s);
    fix_select_kernel<<<6, 256>>>(out);
    gemm2_mma_kernel<<<dim3(4, ROWS2 / 128, KSPLIT), 256, SMEM_PIPE>>>(chart_h);
    combine_normalize_kernel<<<ROWS2, 256>>>(bc, out);
}